// round 8
// baseline (speedup 1.0000x reference)
#include <cuda_runtime.h>
#include <cuda_fp16.h>
#include <cstdint>

#define N_TOKENS 4096
#define D_IN     4096
#define D_HIDDEN 32768
#define TOPK     64
#define MARGIN   5e-3f

// ---------------- device scratch (no allocations allowed) -------------------
__device__ __half g_x1[(size_t)N_TOKENS * D_IN];
__device__ __half g_w1[(size_t)D_HIDDEN * D_IN];
__device__ __half g_wdecT[(size_t)D_HIDDEN * D_IN];   // fp16 transposed decoder
__device__ int   g_topk_idx[N_TOKENS * TOPK];
__device__ float g_topk_val[N_TOKENS * TOPK];
__device__ int   g_cand_idx[N_TOKENS * 64];
__device__ float g_cand_val[N_TOKENS * 64];
__device__ int   g_ndef[N_TOKENS];
__device__ int   g_ncand[N_TOKENS];

// ---------------- helpers ----------------------------------------------------
__device__ __forceinline__ uint32_t smem_u32(const void* p) {
    uint32_t a;
    asm("{ .reg .u64 t; cvta.to.shared.u64 t, %1; cvt.u32.u64 %0, t; }" : "=r"(a) : "l"(p));
    return a;
}
__device__ __forceinline__ void cp16(uint32_t saddr, const void* gaddr) {
    asm volatile("cp.async.cg.shared.global [%0], [%1], 16;" :: "r"(saddr), "l"(gaddr));
}
#define CP_COMMIT()  asm volatile("cp.async.commit_group;" ::: "memory")
#define CP_WAIT0()   asm volatile("cp.async.wait_group 0;" ::: "memory")
#define CP_WAIT1()   asm volatile("cp.async.wait_group 1;" ::: "memory")

#define LDSM_X4(d, addr) \
    asm volatile("ldmatrix.sync.aligned.m8n8.x4.shared.b16 {%0,%1,%2,%3}, [%4];" \
        : "=r"((d)[0]), "=r"((d)[1]), "=r"((d)[2]), "=r"((d)[3]) : "r"(addr))

__device__ __forceinline__ void mma16816(float* d, const uint32_t* a, uint32_t b0, uint32_t b1) {
    asm volatile("mma.sync.aligned.m16n8k16.row.col.f32.f16.f16.f32 "
        "{%0,%1,%2,%3}, {%4,%5,%6,%7}, {%8,%9}, {%0,%1,%2,%3};"
        : "+f"(d[0]), "+f"(d[1]), "+f"(d[2]), "+f"(d[3])
        : "r"(a[0]), "r"(a[1]), "r"(a[2]), "r"(a[3]), "r"(b0), "r"(b1));
}

// ---------------- convert kernels (fp32 -> fp16) ----------------------------
__global__ __launch_bounds__(256)
void split_x_kernel(const float* __restrict__ src)
{
    size_t i = ((size_t)blockIdx.x * 256 + threadIdx.x) * 4;
    if (i >= (size_t)N_TOKENS * D_IN) return;
    float4 v = *(const float4*)(src + i);
    *(__half2*)(g_x1 + i)     = __half2{__float2half_rn(v.x), __float2half_rn(v.y)};
    *(__half2*)(g_x1 + i + 2) = __half2{__float2half_rn(v.z), __float2half_rn(v.w)};
}

__global__ __launch_bounds__(256)
void split_w_kernel(const float* __restrict__ src)
{
    size_t i = ((size_t)blockIdx.x * 256 + threadIdx.x) * 4;
    if (i >= (size_t)D_HIDDEN * D_IN) return;
    float4 v = *(const float4*)(src + i);
    *(__half2*)(g_w1 + i)     = __half2{__float2half_rn(v.x), __float2half_rn(v.y)};
    *(__half2*)(g_w1 + i + 2) = __half2{__float2half_rn(v.z), __float2half_rn(v.w)};
}

// ---------------- encode: fp16 x*w GEMM on mma.sync -------------------------
// CTA tile 128(tok) x 256(hid), BK=64, 8 warps 2x4, warp tile 64x64.
// B fragments via ldmatrix.x4 covering two n8 tiles -> 8 ldsm / 32 MMA per k16.
// SMEM stage: X(16KB)|W(32KB), 3-stage cp.async ring (144KB).
#define EBK 64
#define X_BYTES 16384
#define W_BYTES 32768
#define STAGE_BYTES (X_BYTES + W_BYTES)   // 48KB
#define ENC_SMEM (3 * STAGE_BYTES)        // 144KB
#define N_STAGES (D_IN / EBK)             // 64

__global__ __launch_bounds__(256, 1)
void encode_mma_kernel(const float* __restrict__ bias, float* __restrict__ feat)
{
    extern __shared__ __align__(128) char smem[];
    const int tid  = threadIdx.x;
    const int wid  = tid >> 5;
    const int lane = tid & 31;
    const int wm   = wid >> 2;       // 0..1 (token halves)
    const int wn   = wid & 3;        // 0..3 (hidden quarters)
    const int bn   = blockIdx.x * 128;
    const int bh   = blockIdx.y * 256;
    const uint32_t smem_base = smem_u32(smem);

    float acc[4][8][4];
#pragma unroll
    for (int mt = 0; mt < 4; ++mt)
#pragma unroll
        for (int nt = 0; nt < 8; ++nt)
#pragma unroll
            for (int q = 0; q < 4; ++q) acc[mt][nt][q] = 0.0f;

#define PREFETCH(s) do {                                                          \
    const int _k0 = (s) * EBK;                                                    \
    const uint32_t _st = smem_base + ((s) % 3) * STAGE_BYTES;                     \
    _Pragma("unroll")                                                             \
    for (int _l = 0; _l < 4; ++_l) {                                              \
        int _id = _l * 256 + tid;            /* 0..1023: X 128 rows x 8 chunks */ \
        int _r = _id >> 3, _c = _id & 7;                                          \
        uint32_t _sw = (uint32_t)(_r * 128 + ((_c ^ (_r & 7)) << 4));             \
        cp16(_st + _sw, g_x1 + (size_t)(bn + _r) * D_IN + _k0 + _c * 8);          \
    }                                                                             \
    _Pragma("unroll")                                                             \
    for (int _l = 0; _l < 8; ++_l) {                                              \
        int _id = _l * 256 + tid;            /* 0..2047: W 256 rows x 8 chunks */ \
        int _r = _id >> 3, _c = _id & 7;                                          \
        uint32_t _sw = (uint32_t)(_r * 128 + ((_c ^ (_r & 7)) << 4));             \
        cp16(_st + X_BYTES + _sw, g_w1 + (size_t)(bh + _r) * D_IN + _k0 + _c * 8);\
    }                                                                             \
    CP_COMMIT();                                                                  \
} while (0)

    PREFETCH(0);
    PREFETCH(1);

    const int l7   = lane & 7;
    const int cxor = lane >> 4;                       // chunk offset from lane
    const int rA   = wm * 64 + (lane & 15);           // A row (per mt: +16)
    const int rB   = wn * 64 + ((lane >> 3) & 1) * 8 + l7;   // B row (per nt: +16)

    for (int s = 0; s < N_STAGES; ++s) {
        if (s + 2 < N_STAGES) {
            CP_WAIT1();
            __syncthreads();
            PREFETCH(s + 2);
        } else {
            CP_WAIT0();
            __syncthreads();
        }
        const uint32_t st = smem_base + (s % 3) * STAGE_BYTES;

#pragma unroll
        for (int ks = 0; ks < 4; ++ks) {
            const int c = 2 * ks + cxor;
            const uint32_t sw = (uint32_t)((c ^ l7) << 4);
            uint32_t a[4][4], b[4][4];
#pragma unroll
            for (int mt = 0; mt < 4; ++mt) {
                uint32_t off = st + (uint32_t)((rA + mt * 16) * 128) + sw;
                LDSM_X4(a[mt], off);
            }
#pragma unroll
            for (int nt = 0; nt < 4; ++nt) {
                uint32_t off = st + X_BYTES + (uint32_t)((rB + nt * 16) * 128) + sw;
                LDSM_X4(b[nt], off);   // b[nt] = {b0(n0), b0(n1), b1(n0), b1(n1)}
            }
#pragma unroll
            for (int mt = 0; mt < 4; ++mt)
#pragma unroll
                for (int nt = 0; nt < 4; ++nt) {
                    mma16816(acc[mt][2 * nt],     a[mt], b[nt][0], b[nt][2]);
                    mma16816(acc[mt][2 * nt + 1], a[mt], b[nt][1], b[nt][3]);
                }
        }
        // no bottom barrier: top barrier of iter s+1 orders buffer reuse
    }
#undef PREFETCH

    // Epilogue: +bias, ReLU, store fp32
#pragma unroll
    for (int mt = 0; mt < 4; ++mt) {
        const int row0 = bn + wm * 64 + mt * 16 + (lane >> 2);
#pragma unroll
        for (int nt = 0; nt < 8; ++nt) {
            const int col0 = bh + wn * 64 + nt * 8 + (lane & 3) * 2;
            const float bb0 = bias[col0], bb1 = bias[col0 + 1];
            float2 v0, v1;
            v0.x = acc[mt][nt][0] + bb0; v0.x = v0.x > 0.0f ? v0.x : 0.0f;
            v0.y = acc[mt][nt][1] + bb1; v0.y = v0.y > 0.0f ? v0.y : 0.0f;
            v1.x = acc[mt][nt][2] + bb0; v1.x = v1.x > 0.0f ? v1.x : 0.0f;
            v1.y = acc[mt][nt][3] + bb1; v1.y = v1.y > 0.0f ? v1.y : 0.0f;
            *(float2*)&feat[(size_t)row0 * D_HIDDEN + col0]       = v0;
            *(float2*)&feat[(size_t)(row0 + 8) * D_HIDDEN + col0] = v1;
        }
    }
}

// ---------------- top-k: 1-pass linear histogram + margin classify ----------
__global__ __launch_bounds__(256)
void topk_kernel(float* __restrict__ feat)
{
    const int n   = blockIdx.x;
    const int tid = threadIdx.x;
    float* row = feat + (size_t)n * D_HIDDEN;

    __shared__ int hist[4096];
    __shared__ int s_part[256];
    __shared__ int s_bin;
    __shared__ int s_ndef, s_ncand;

    for (int i = tid; i < 4096; i += 256) hist[i] = 0;
    if (tid == 0) { s_bin = 0; s_ndef = 0; s_ncand = 0; }
    __syncthreads();

    for (int i = tid; i < D_HIDDEN; i += 256) {
        float v = row[i];
        if (v > 0.0f) {
            int b = (int)(v * 512.0f);
            if (b > 4095) b = 4095;
            atomicAdd(&hist[b], 1);
        }
    }
    __syncthreads();

    const int hi_b = 4095 - tid * 16;
    int part = 0;
#pragma unroll
    for (int j = 0; j < 16; ++j) part += hist[hi_b - j];
    s_part[tid] = part;
    __syncthreads();
    for (int off = 1; off < 256; off <<= 1) {
        int v2 = (tid >= off) ? s_part[tid - off] : 0;
        __syncthreads();
        s_part[tid] += v2;
        __syncthreads();
    }
    const int incl = s_part[tid];
    const int excl = incl - part;
    if (excl < TOPK && incl >= TOPK) {
        int cum = excl;
        for (int j = 0; j < 16; ++j) {
            cum += hist[hi_b - j];
            if (cum >= TOPK) { s_bin = hi_b - j; break; }
        }
    }
    __syncthreads();

    const float lo = (float)s_bin / 512.0f - MARGIN;
    const float hi = (float)(s_bin + 1) / 512.0f + MARGIN;

    for (int i = tid; i < D_HIDDEN; i += 256) {
        float v = row[i];
        if (v > hi) {
            int p = atomicAdd(&s_ndef, 1);
            g_topk_idx[n * TOPK + p] = i;
            g_topk_val[n * TOPK + p] = v;
        } else {
            if (v >= lo) {
                int q = atomicAdd(&s_ncand, 1);
                if (q < 64) { g_cand_idx[n * 64 + q] = i; g_cand_val[n * 64 + q] = v; }
            }
            row[i] = 0.0f;
        }
    }
    __syncthreads();
    if (tid == 0) {
        g_ndef[n]  = s_ndef;
        g_ncand[n] = s_ncand < 64 ? s_ncand : 64;
    }
}

// ---------------- rerank: exact fp64 scoring of boundary candidates ---------
__global__ __launch_bounds__(256)
void rerank_kernel(const float* __restrict__ x, const float* __restrict__ W_enc,
                   const float* __restrict__ b_enc, float* __restrict__ feat)
{
    __shared__ float  sx[D_IN];
    __shared__ double sred[256];
    __shared__ double s_exact[64];

    const int n   = blockIdx.x;
    const int tid = threadIdx.x;
    const int ndef  = g_ndef[n];
    const int ncand = g_ncand[n];
    const int need  = TOPK - ndef;
    float* row = feat + (size_t)n * D_HIDDEN;

    if (need <= 0) return;

    if (ncand <= need) {
        for (int c = tid; c < ncand; c += 256) {
            int idx = g_cand_idx[n * 64 + c];
            float v = g_cand_val[n * 64 + c];
            row[idx] = v;
            g_topk_idx[n * TOPK + ndef + c] = idx;
            g_topk_val[n * TOPK + ndef + c] = v;
        }
        return;
    }

    for (int i = tid * 4; i < D_IN; i += 1024)
        *(float4*)&sx[i] = *(const float4*)(x + (size_t)n * D_IN + i);
    __syncthreads();

    for (int c = 0; c < ncand; ++c) {
        const float* w = W_enc + (size_t)g_cand_idx[n * 64 + c] * D_IN;
        double acc = 0.0;
        for (int j = tid; j < D_IN; j += 256)
            acc += (double)sx[j] * (double)w[j];
        sred[tid] = acc;
        __syncthreads();
        for (int st = 128; st > 0; st >>= 1) {
            if (tid < st) sred[tid] += sred[tid + st];
            __syncthreads();
        }
        if (tid == 0) {
            double v = sred[0] + (double)b_enc[g_cand_idx[n * 64 + c]];
            s_exact[c] = v > 0.0 ? v : 0.0;
        }
        __syncthreads();
    }

    if (tid == 0) {
        bool used[64];
        for (int c = 0; c < ncand; ++c) used[c] = false;
        for (int r = 0; r < need; ++r) {
            int best = -1;
            for (int c = 0; c < ncand; ++c) {
                if (used[c]) continue;
                if (best < 0 || s_exact[c] > s_exact[best] ||
                    (s_exact[c] == s_exact[best] &&
                     g_cand_idx[n * 64 + c] < g_cand_idx[n * 64 + best]))
                    best = c;
            }
            used[best] = true;
            int idx = g_cand_idx[n * 64 + best];
            float v = g_cand_val[n * 64 + best];
            row[idx] = v;
            g_topk_idx[n * TOPK + ndef + r] = idx;
            g_topk_val[n * TOPK + ndef + r] = v;
        }
    }
}

// ---------------- transpose W_dec [d][h] -> g_wdecT fp16 [h][d] -------------
// Tile: 32 hidden x 64 d. Reads/writes both 128B-coalesced per warp row.
__global__ __launch_bounds__(256)
void transpose_kernel(const float* __restrict__ W)
{
    __shared__ float t[32][65];     // [h][d]
    const int h0 = blockIdx.x * 32;
    const int d0 = blockIdx.y * 64;
    const int tx = threadIdx.x;     // 0..31
    const int ty = threadIdx.y;     // 0..7

#pragma unroll
    for (int i = 0; i < 64; i += 8)
        t[tx][i + ty] = W[(size_t)(d0 + i + ty) * D_HIDDEN + h0 + tx];
    __syncthreads();
#pragma unroll
    for (int i = 0; i < 32; i += 8) {
        const int h = i + ty;
        __half2 hv = __half2{__float2half_rn(t[h][2 * tx]),
                             __float2half_rn(t[h][2 * tx + 1])};
        *(__half2*)(g_wdecT + (size_t)(h0 + h) * D_IN + d0 + 2 * tx) = hv;
    }
}

// ---------------- sparse decode (fp16 weights, fp32 accum) ------------------
__global__ __launch_bounds__(256)
void decode_kernel(float* __restrict__ recon, const float* __restrict__ b_dec)
{
    const int n   = blockIdx.x;
    const int tid = threadIdx.x;

    __shared__ int   s_idx[TOPK];
    __shared__ float s_val[TOPK];
    if (tid < TOPK) {
        s_idx[tid] = g_topk_idx[n * TOPK + tid];
        s_val[tid] = g_topk_val[n * TOPK + tid];
    }
    __syncthreads();

    float acc[16];
#pragma unroll
    for (int r = 0; r < 8; ++r) {
        float2 b = *(const float2*)(b_dec + 2 * (tid + r * 256));
        acc[2 * r] = b.x; acc[2 * r + 1] = b.y;
    }

    for (int j = 0; j < TOPK; ++j) {
        const __half2* wr = (const __half2*)(g_wdecT + (size_t)s_idx[j] * D_IN);
        const float v = s_val[j];
#pragma unroll
        for (int r = 0; r < 8; ++r) {
            float2 w = __half22float2(wr[tid + r * 256]);
            acc[2 * r]     += v * w.x;
            acc[2 * r + 1] += v * w.y;
        }
    }

    float* out = recon + (size_t)n * D_IN;
#pragma unroll
    for (int r = 0; r < 8; ++r) {
        float2 o; o.x = acc[2 * r]; o.y = acc[2 * r + 1];
        *(float2*)(out + 2 * (tid + r * 256)) = o;
    }
}

// ---------------- launch -----------------------------------------------------
extern "C" void kernel_launch(void* const* d_in, const int* in_sizes, int n_in,
                              void* d_out, int out_size)
{
    const float* x     = (const float*)d_in[0];
    const float* W_enc = (const float*)d_in[1];
    const float* b_enc = (const float*)d_in[2];
    const float* W_dec = (const float*)d_in[3];
    const float* b_dec = (const float*)d_in[4];

    float* recon = (float*)d_out;
    float* feat  = (float*)d_out + (size_t)N_TOKENS * D_IN;

    cudaFuncSetAttribute(encode_mma_kernel,
                         cudaFuncAttributeMaxDynamicSharedMemorySize, ENC_SMEM);

    split_x_kernel<<<(N_TOKENS * D_IN) / 1024, 256>>>(x);
    split_w_kernel<<<((size_t)D_HIDDEN * D_IN) / 1024, 256>>>(W_enc);
    transpose_kernel<<<dim3(D_HIDDEN / 32, D_IN / 64), dim3(32, 8)>>>(W_dec);

    encode_mma_kernel<<<dim3(N_TOKENS / 128, D_HIDDEN / 256), 256, ENC_SMEM>>>(b_enc, feat);

    topk_kernel<<<N_TOKENS, 256>>>(feat);
    rerank_kernel<<<N_TOKENS, 256>>>(x, W_enc, b_enc, feat);
    decode_kernel<<<N_TOKENS, 256>>>(recon, b_dec);
}

// round 9
// speedup vs baseline: 1.0030x; 1.0030x over previous
#include <cuda_runtime.h>
#include <cuda_fp16.h>
#include <cstdint>

#define N_TOKENS 4096
#define D_IN     4096
#define D_HIDDEN 32768
#define TOPK     64
#define MARGIN   5e-3f

// ---------------- device scratch (no allocations allowed) -------------------
__device__ __half g_x1[(size_t)N_TOKENS * D_IN];
__device__ __half g_w1[(size_t)D_HIDDEN * D_IN];
__device__ __half g_wdecT[(size_t)D_HIDDEN * D_IN];   // fp16 transposed decoder
__device__ int   g_topk_idx[N_TOKENS * TOPK];
__device__ float g_topk_val[N_TOKENS * TOPK];
__device__ int   g_cand_idx[N_TOKENS * 64];
__device__ float g_cand_val[N_TOKENS * 64];
__device__ int   g_ndef[N_TOKENS];
__device__ int   g_ncand[N_TOKENS];

// ---------------- helpers ----------------------------------------------------
__device__ __forceinline__ uint32_t smem_u32(const void* p) {
    uint32_t a;
    asm("{ .reg .u64 t; cvta.to.shared.u64 t, %1; cvt.u32.u64 %0, t; }" : "=r"(a) : "l"(p));
    return a;
}
__device__ __forceinline__ void cp16(uint32_t saddr, const void* gaddr) {
    asm volatile("cp.async.cg.shared.global [%0], [%1], 16;" :: "r"(saddr), "l"(gaddr));
}
#define CP_COMMIT()  asm volatile("cp.async.commit_group;" ::: "memory")
#define CP_WAIT0()   asm volatile("cp.async.wait_group 0;" ::: "memory")
#define CP_WAIT1()   asm volatile("cp.async.wait_group 1;" ::: "memory")

#define LDSM_X4(d, addr) \
    asm volatile("ldmatrix.sync.aligned.m8n8.x4.shared.b16 {%0,%1,%2,%3}, [%4];" \
        : "=r"((d)[0]), "=r"((d)[1]), "=r"((d)[2]), "=r"((d)[3]) : "r"(addr))

__device__ __forceinline__ void mma16816(float* d, const uint32_t* a, uint32_t b0, uint32_t b1) {
    asm volatile("mma.sync.aligned.m16n8k16.row.col.f32.f16.f16.f32 "
        "{%0,%1,%2,%3}, {%4,%5,%6,%7}, {%8,%9}, {%0,%1,%2,%3};"
        : "+f"(d[0]), "+f"(d[1]), "+f"(d[2]), "+f"(d[3])
        : "r"(a[0]), "r"(a[1]), "r"(a[2]), "r"(a[3]), "r"(b0), "r"(b1));
}

// ---------------- convert kernels (fp32 -> fp16) ----------------------------
__global__ __launch_bounds__(256)
void split_x_kernel(const float* __restrict__ src)
{
    size_t i = ((size_t)blockIdx.x * 256 + threadIdx.x) * 4;
    if (i >= (size_t)N_TOKENS * D_IN) return;
    float4 v = *(const float4*)(src + i);
    *(__half2*)(g_x1 + i)     = __half2{__float2half_rn(v.x), __float2half_rn(v.y)};
    *(__half2*)(g_x1 + i + 2) = __half2{__float2half_rn(v.z), __float2half_rn(v.w)};
}

__global__ __launch_bounds__(256)
void split_w_kernel(const float* __restrict__ src)
{
    size_t i = ((size_t)blockIdx.x * 256 + threadIdx.x) * 4;
    if (i >= (size_t)D_HIDDEN * D_IN) return;
    float4 v = *(const float4*)(src + i);
    *(__half2*)(g_w1 + i)     = __half2{__float2half_rn(v.x), __float2half_rn(v.y)};
    *(__half2*)(g_w1 + i + 2) = __half2{__float2half_rn(v.z), __float2half_rn(v.w)};
}

// ---------------- encode: fp16 x*w GEMM on mma.sync -------------------------
// R7 winning config: CTA tile 128x128, BK=64, 8 warps 2x4, warp tile 64x32,
// 3-stage cp.async ring (96KB), 2 CTAs/SM. Only change vs R7: B fragments via
// 2x ldmatrix.x4 (covering two n8 tiles each) instead of 4x ldmatrix.x2.
#define EBK 64
#define ARR_BYTES 16384
#define STAGE_BYTES (2 * ARR_BYTES)      // 32KB
#define ENC_SMEM (3 * STAGE_BYTES)       // 96KB
#define N_STAGES (D_IN / EBK)            // 64

__global__ __launch_bounds__(256, 2)
void encode_mma_kernel(const float* __restrict__ bias, float* __restrict__ feat)
{
    extern __shared__ __align__(128) char smem[];
    const int tid  = threadIdx.x;
    const int wid  = tid >> 5;
    const int lane = tid & 31;
    const int wm   = wid >> 2;       // 0..1
    const int wn   = wid & 3;        // 0..3
    const int bn   = blockIdx.x * 128;   // token tile (fastest -> B tile L2-hot)
    const int bh   = blockIdx.y * 128;   // hidden tile
    const uint32_t smem_base = smem_u32(smem);

    float acc[4][4][4];
#pragma unroll
    for (int mt = 0; mt < 4; ++mt)
#pragma unroll
        for (int nt = 0; nt < 4; ++nt)
#pragma unroll
            for (int q = 0; q < 4; ++q) acc[mt][nt][q] = 0.0f;

#define PREFETCH(s) do {                                                          \
    const int _k0 = (s) * EBK;                                                    \
    const uint32_t _st = smem_base + ((s) % 3) * STAGE_BYTES;                     \
    _Pragma("unroll")                                                             \
    for (int _l = 0; _l < 4; ++_l) {                                              \
        int _id = _l * 256 + tid;                                                 \
        int _r = _id >> 3, _c = _id & 7;                                          \
        uint32_t _sw = (uint32_t)(_r * 128 + ((_c ^ (_r & 7)) << 4));             \
        size_t _ga = (size_t)(bn + _r) * D_IN + _k0 + _c * 8;                     \
        size_t _gb = (size_t)(bh + _r) * D_IN + _k0 + _c * 8;                     \
        cp16(_st + 0 * ARR_BYTES + _sw, g_x1 + _ga);                              \
        cp16(_st + 1 * ARR_BYTES + _sw, g_w1 + _gb);                              \
    }                                                                             \
    CP_COMMIT();                                                                  \
} while (0)

    PREFETCH(0);
    PREFETCH(1);

    const int l7   = lane & 7;
    const int cxor = lane >> 4;                         // chunk offset from lane
    const int rA   = wm * 64 + (lane & 15);             // A rows (per mt: +16)
    const int rB   = wn * 32 + ((lane >> 3) & 1) * 8 + l7;  // B rows (per nt: +16)

    for (int s = 0; s < N_STAGES; ++s) {
        if (s + 2 < N_STAGES) {
            CP_WAIT1();
            __syncthreads();
            PREFETCH(s + 2);
        } else {
            CP_WAIT0();
            __syncthreads();
        }
        const uint32_t st = smem_base + (s % 3) * STAGE_BYTES;

#pragma unroll
        for (int ks = 0; ks < 4; ++ks) {
            const int c = 2 * ks + cxor;
            uint32_t a[4][4], b[2][4];
#pragma unroll
            for (int mt = 0; mt < 4; ++mt) {
                int r = rA + mt * 16;
                uint32_t off = st + (uint32_t)(r * 128 + ((c ^ (r & 7)) << 4));
                LDSM_X4(a[mt], off);
            }
#pragma unroll
            for (int nt = 0; nt < 2; ++nt) {
                int r = rB + nt * 16;
                uint32_t off = st + ARR_BYTES + (uint32_t)(r * 128 + ((c ^ l7) << 4));
                LDSM_X4(b[nt], off);  // {n(2nt) klo, n(2nt+1) klo, n(2nt) khi, n(2nt+1) khi}
            }
#pragma unroll
            for (int mt = 0; mt < 4; ++mt)
#pragma unroll
                for (int nt = 0; nt < 2; ++nt) {
                    mma16816(acc[mt][2 * nt],     a[mt], b[nt][0], b[nt][2]);
                    mma16816(acc[mt][2 * nt + 1], a[mt], b[nt][1], b[nt][3]);
                }
        }
        __syncthreads();
    }
#undef PREFETCH

    // Epilogue: +bias, ReLU, store fp32
#pragma unroll
    for (int mt = 0; mt < 4; ++mt) {
        const int row0 = bn + wm * 64 + mt * 16 + (lane >> 2);
#pragma unroll
        for (int nt = 0; nt < 4; ++nt) {
            const int col0 = bh + wn * 32 + nt * 8 + (lane & 3) * 2;
            const float bb0 = bias[col0], bb1 = bias[col0 + 1];
            float2 v0, v1;
            v0.x = acc[mt][nt][0] + bb0; v0.x = v0.x > 0.0f ? v0.x : 0.0f;
            v0.y = acc[mt][nt][1] + bb1; v0.y = v0.y > 0.0f ? v0.y : 0.0f;
            v1.x = acc[mt][nt][2] + bb0; v1.x = v1.x > 0.0f ? v1.x : 0.0f;
            v1.y = acc[mt][nt][3] + bb1; v1.y = v1.y > 0.0f ? v1.y : 0.0f;
            *(float2*)&feat[(size_t)row0 * D_HIDDEN + col0]       = v0;
            *(float2*)&feat[(size_t)(row0 + 8) * D_HIDDEN + col0] = v1;
        }
    }
}

// ---------------- top-k: 1-pass linear histogram + margin classify ----------
__global__ __launch_bounds__(256)
void topk_kernel(float* __restrict__ feat)
{
    const int n   = blockIdx.x;
    const int tid = threadIdx.x;
    float* row = feat + (size_t)n * D_HIDDEN;

    __shared__ int hist[4096];
    __shared__ int s_part[256];
    __shared__ int s_bin;
    __shared__ int s_ndef, s_ncand;

    for (int i = tid; i < 4096; i += 256) hist[i] = 0;
    if (tid == 0) { s_bin = 0; s_ndef = 0; s_ncand = 0; }
    __syncthreads();

    for (int i = tid; i < D_HIDDEN; i += 256) {
        float v = row[i];
        if (v > 0.0f) {
            int b = (int)(v * 512.0f);
            if (b > 4095) b = 4095;
            atomicAdd(&hist[b], 1);
        }
    }
    __syncthreads();

    const int hi_b = 4095 - tid * 16;
    int part = 0;
#pragma unroll
    for (int j = 0; j < 16; ++j) part += hist[hi_b - j];
    s_part[tid] = part;
    __syncthreads();
    for (int off = 1; off < 256; off <<= 1) {
        int v2 = (tid >= off) ? s_part[tid - off] : 0;
        __syncthreads();
        s_part[tid] += v2;
        __syncthreads();
    }
    const int incl = s_part[tid];
    const int excl = incl - part;
    if (excl < TOPK && incl >= TOPK) {
        int cum = excl;
        for (int j = 0; j < 16; ++j) {
            cum += hist[hi_b - j];
            if (cum >= TOPK) { s_bin = hi_b - j; break; }
        }
    }
    __syncthreads();

    const float lo = (float)s_bin / 512.0f - MARGIN;
    const float hi = (float)(s_bin + 1) / 512.0f + MARGIN;

    for (int i = tid; i < D_HIDDEN; i += 256) {
        float v = row[i];
        if (v > hi) {
            int p = atomicAdd(&s_ndef, 1);
            g_topk_idx[n * TOPK + p] = i;
            g_topk_val[n * TOPK + p] = v;
        } else {
            if (v >= lo) {
                int q = atomicAdd(&s_ncand, 1);
                if (q < 64) { g_cand_idx[n * 64 + q] = i; g_cand_val[n * 64 + q] = v; }
            }
            row[i] = 0.0f;
        }
    }
    __syncthreads();
    if (tid == 0) {
        g_ndef[n]  = s_ndef;
        g_ncand[n] = s_ncand < 64 ? s_ncand : 64;
    }
}

// ---------------- rerank: exact fp64 scoring of boundary candidates ---------
__global__ __launch_bounds__(256)
void rerank_kernel(const float* __restrict__ x, const float* __restrict__ W_enc,
                   const float* __restrict__ b_enc, float* __restrict__ feat)
{
    __shared__ float  sx[D_IN];
    __shared__ double sred[256];
    __shared__ double s_exact[64];

    const int n   = blockIdx.x;
    const int tid = threadIdx.x;
    const int ndef  = g_ndef[n];
    const int ncand = g_ncand[n];
    const int need  = TOPK - ndef;
    float* row = feat + (size_t)n * D_HIDDEN;

    if (need <= 0) return;

    if (ncand <= need) {
        for (int c = tid; c < ncand; c += 256) {
            int idx = g_cand_idx[n * 64 + c];
            float v = g_cand_val[n * 64 + c];
            row[idx] = v;
            g_topk_idx[n * TOPK + ndef + c] = idx;
            g_topk_val[n * TOPK + ndef + c] = v;
        }
        return;
    }

    for (int i = tid * 4; i < D_IN; i += 1024)
        *(float4*)&sx[i] = *(const float4*)(x + (size_t)n * D_IN + i);
    __syncthreads();

    for (int c = 0; c < ncand; ++c) {
        const float* w = W_enc + (size_t)g_cand_idx[n * 64 + c] * D_IN;
        double acc = 0.0;
        for (int j = tid; j < D_IN; j += 256)
            acc += (double)sx[j] * (double)w[j];
        sred[tid] = acc;
        __syncthreads();
        for (int st = 128; st > 0; st >>= 1) {
            if (tid < st) sred[tid] += sred[tid + st];
            __syncthreads();
        }
        if (tid == 0) {
            double v = sred[0] + (double)b_enc[g_cand_idx[n * 64 + c]];
            s_exact[c] = v > 0.0 ? v : 0.0;
        }
        __syncthreads();
    }

    if (tid == 0) {
        bool used[64];
        for (int c = 0; c < ncand; ++c) used[c] = false;
        for (int r = 0; r < need; ++r) {
            int best = -1;
            for (int c = 0; c < ncand; ++c) {
                if (used[c]) continue;
                if (best < 0 || s_exact[c] > s_exact[best] ||
                    (s_exact[c] == s_exact[best] &&
                     g_cand_idx[n * 64 + c] < g_cand_idx[n * 64 + best]))
                    best = c;
            }
            used[best] = true;
            int idx = g_cand_idx[n * 64 + best];
            float v = g_cand_val[n * 64 + best];
            row[idx] = v;
            g_topk_idx[n * TOPK + ndef + r] = idx;
            g_topk_val[n * TOPK + ndef + r] = v;
        }
    }
}

// ---------------- transpose W_dec [d][h] -> g_wdecT fp16 [h][d] -------------
__global__ __launch_bounds__(256)
void transpose_kernel(const float* __restrict__ W)
{
    __shared__ float t[32][65];     // [h][d]
    const int h0 = blockIdx.x * 32;
    const int d0 = blockIdx.y * 64;
    const int tx = threadIdx.x;     // 0..31
    const int ty = threadIdx.y;     // 0..7

#pragma unroll
    for (int i = 0; i < 64; i += 8)
        t[tx][i + ty] = W[(size_t)(d0 + i + ty) * D_HIDDEN + h0 + tx];
    __syncthreads();
#pragma unroll
    for (int i = 0; i < 32; i += 8) {
        const int h = i + ty;
        __half2 hv = __half2{__float2half_rn(t[h][2 * tx]),
                             __float2half_rn(t[h][2 * tx + 1])};
        *(__half2*)(g_wdecT + (size_t)(h0 + h) * D_IN + d0 + 2 * tx) = hv;
    }
}

// ---------------- sparse decode (fp16 weights, fp32 accum) ------------------
__global__ __launch_bounds__(256)
void decode_kernel(float* __restrict__ recon, const float* __restrict__ b_dec)
{
    const int n   = blockIdx.x;
    const int tid = threadIdx.x;

    __shared__ int   s_idx[TOPK];
    __shared__ float s_val[TOPK];
    if (tid < TOPK) {
        s_idx[tid] = g_topk_idx[n * TOPK + tid];
        s_val[tid] = g_topk_val[n * TOPK + tid];
    }
    __syncthreads();

    float acc[16];
#pragma unroll
    for (int r = 0; r < 8; ++r) {
        float2 b = *(const float2*)(b_dec + 2 * (tid + r * 256));
        acc[2 * r] = b.x; acc[2 * r + 1] = b.y;
    }

    for (int j = 0; j < TOPK; ++j) {
        const __half2* wr = (const __half2*)(g_wdecT + (size_t)s_idx[j] * D_IN);
        const float v = s_val[j];
#pragma unroll
        for (int r = 0; r < 8; ++r) {
            float2 w = __half22float2(wr[tid + r * 256]);
            acc[2 * r]     += v * w.x;
            acc[2 * r + 1] += v * w.y;
        }
    }

    float* out = recon + (size_t)n * D_IN;
#pragma unroll
    for (int r = 0; r < 8; ++r) {
        float2 o; o.x = acc[2 * r]; o.y = acc[2 * r + 1];
        *(float2*)(out + 2 * (tid + r * 256)) = o;
    }
}

// ---------------- launch -----------------------------------------------------
extern "C" void kernel_launch(void* const* d_in, const int* in_sizes, int n_in,
                              void* d_out, int out_size)
{
    const float* x     = (const float*)d_in[0];
    const float* W_enc = (const float*)d_in[1];
    const float* b_enc = (const float*)d_in[2];
    const float* W_dec = (const float*)d_in[3];
    const float* b_dec = (const float*)d_in[4];

    float* recon = (float*)d_out;
    float* feat  = (float*)d_out + (size_t)N_TOKENS * D_IN;

    cudaFuncSetAttribute(encode_mma_kernel,
                         cudaFuncAttributeMaxDynamicSharedMemorySize, ENC_SMEM);

    split_x_kernel<<<(N_TOKENS * D_IN) / 1024, 256>>>(x);
    split_w_kernel<<<((size_t)D_HIDDEN * D_IN) / 1024, 256>>>(W_enc);
    transpose_kernel<<<dim3(D_HIDDEN / 32, D_IN / 64), dim3(32, 8)>>>(W_dec);

    encode_mma_kernel<<<dim3(N_TOKENS / 128, D_HIDDEN / 128), 256, ENC_SMEM>>>(b_enc, feat);

    topk_kernel<<<N_TOKENS, 256>>>(feat);
    rerank_kernel<<<N_TOKENS, 256>>>(x, W_enc, b_enc, feat);
    decode_kernel<<<N_TOKENS, 256>>>(recon, b_dec);
}

// round 10
// speedup vs baseline: 1.1138x; 1.1105x over previous
#include <cuda_runtime.h>
#include <cuda_fp16.h>
#include <cstdint>

#define N_TOKENS 4096
#define D_IN     4096
#define D_HIDDEN 32768
#define TOPK     64
#define MARGIN   5e-3f

// ---------------- device scratch (no allocations allowed) -------------------
__device__ __half g_x1[(size_t)N_TOKENS * D_IN];
__device__ __half g_w1[(size_t)D_HIDDEN * D_IN];
__device__ __half g_wdecT[(size_t)D_HIDDEN * D_IN];   // fp16 transposed decoder
__device__ int   g_topk_idx[N_TOKENS * TOPK];
__device__ float g_topk_val[N_TOKENS * TOPK];
__device__ int   g_cand_idx[N_TOKENS * 64];
__device__ float g_cand_val[N_TOKENS * 64];
__device__ int   g_ndef[N_TOKENS];
__device__ int   g_ncand[N_TOKENS];

// ---------------- helpers ----------------------------------------------------
__device__ __forceinline__ uint32_t smem_u32(const void* p) {
    uint32_t a;
    asm("{ .reg .u64 t; cvta.to.shared.u64 t, %1; cvt.u32.u64 %0, t; }" : "=r"(a) : "l"(p));
    return a;
}
__device__ __forceinline__ void cp16(uint32_t saddr, const void* gaddr) {
    asm volatile("cp.async.cg.shared.global [%0], [%1], 16;" :: "r"(saddr), "l"(gaddr));
}
#define CP_COMMIT()  asm volatile("cp.async.commit_group;" ::: "memory")
#define CP_WAIT0()   asm volatile("cp.async.wait_group 0;" ::: "memory")
#define CP_WAIT1()   asm volatile("cp.async.wait_group 1;" ::: "memory")

#define LDSM_X4(d, addr) \
    asm volatile("ldmatrix.sync.aligned.m8n8.x4.shared.b16 {%0,%1,%2,%3}, [%4];" \
        : "=r"((d)[0]), "=r"((d)[1]), "=r"((d)[2]), "=r"((d)[3]) : "r"(addr))
#define LDSM_X2(d, addr) \
    asm volatile("ldmatrix.sync.aligned.m8n8.x2.shared.b16 {%0,%1}, [%2];" \
        : "=r"((d)[0]), "=r"((d)[1]) : "r"(addr))

__device__ __forceinline__ void mma16816(float* d, const uint32_t* a, const uint32_t* b) {
    asm volatile("mma.sync.aligned.m16n8k16.row.col.f32.f16.f16.f32 "
        "{%0,%1,%2,%3}, {%4,%5,%6,%7}, {%8,%9}, {%0,%1,%2,%3};"
        : "+f"(d[0]), "+f"(d[1]), "+f"(d[2]), "+f"(d[3])
        : "r"(a[0]), "r"(a[1]), "r"(a[2]), "r"(a[3]), "r"(b[0]), "r"(b[1]));
}

// ---------------- convert kernels (fp32 -> fp16) ----------------------------
__global__ __launch_bounds__(256)
void split_x_kernel(const float* __restrict__ src)
{
    size_t i = ((size_t)blockIdx.x * 256 + threadIdx.x) * 4;
    if (i >= (size_t)N_TOKENS * D_IN) return;
    float4 v = *(const float4*)(src + i);
    *(__half2*)(g_x1 + i)     = __half2{__float2half_rn(v.x), __float2half_rn(v.y)};
    *(__half2*)(g_x1 + i + 2) = __half2{__float2half_rn(v.z), __float2half_rn(v.w)};
}

__global__ __launch_bounds__(256)
void split_w_kernel(const float* __restrict__ src)
{
    size_t i = ((size_t)blockIdx.x * 256 + threadIdx.x) * 4;
    if (i >= (size_t)D_HIDDEN * D_IN) return;
    float4 v = *(const float4*)(src + i);
    *(__half2*)(g_w1 + i)     = __half2{__float2half_rn(v.x), __float2half_rn(v.y)};
    *(__half2*)(g_w1 + i + 2) = __half2{__float2half_rn(v.z), __float2half_rn(v.w)};
}

// ---------------- encode: fp16 x*w GEMM on mma.sync (R7 config, verbatim) ---
// CTA tile 128(tok) x 128(hid), BK=64, 8 warps 2x4, warp tile 64x32.
// SMEM stage: X|W (2 x 16KB, XOR chunk swizzle), 3-stage cp.async pipeline,
// 96KB smem -> 2 CTAs/SM (launch_bounds caps regs at 128).
#define EBK 64
#define ARR_BYTES 16384
#define STAGE_BYTES (2 * ARR_BYTES)      // 32KB
#define ENC_SMEM (3 * STAGE_BYTES)       // 96KB
#define N_STAGES (D_IN / EBK)            // 64

__global__ __launch_bounds__(256, 2)
void encode_mma_kernel(const float* __restrict__ bias, float* __restrict__ feat)
{
    extern __shared__ __align__(128) char smem[];
    const int tid  = threadIdx.x;
    const int wid  = tid >> 5;
    const int lane = tid & 31;
    const int wm   = wid >> 2;       // 0..1
    const int wn   = wid & 3;        // 0..3
    const int bn   = blockIdx.x * 128;   // token tile (fastest -> B tile L2-hot)
    const int bh   = blockIdx.y * 128;   // hidden tile
    const uint32_t smem_base = smem_u32(smem);

    float acc[4][4][4];
#pragma unroll
    for (int mt = 0; mt < 4; ++mt)
#pragma unroll
        for (int nt = 0; nt < 4; ++nt)
#pragma unroll
            for (int q = 0; q < 4; ++q) acc[mt][nt][q] = 0.0f;

#define PREFETCH(s) do {                                                          \
    const int _k0 = (s) * EBK;                                                    \
    const uint32_t _st = smem_base + ((s) % 3) * STAGE_BYTES;                     \
    _Pragma("unroll")                                                             \
    for (int _l = 0; _l < 4; ++_l) {                                              \
        int _id = _l * 256 + tid;                                                 \
        int _r = _id >> 3, _c = _id & 7;                                          \
        uint32_t _sw = (uint32_t)(_r * 128 + ((_c ^ (_r & 7)) << 4));             \
        size_t _ga = (size_t)(bn + _r) * D_IN + _k0 + _c * 8;                     \
        size_t _gb = (size_t)(bh + _r) * D_IN + _k0 + _c * 8;                     \
        cp16(_st + 0 * ARR_BYTES + _sw, g_x1 + _ga);                              \
        cp16(_st + 1 * ARR_BYTES + _sw, g_w1 + _gb);                              \
    }                                                                             \
    CP_COMMIT();                                                                  \
} while (0)

    PREFETCH(0);
    PREFETCH(1);

    const int rA_base = wm * 64 + (lane & 15);
    const int rB_base = wn * 32 + (lane & 7);

    for (int s = 0; s < N_STAGES; ++s) {
        if (s + 2 < N_STAGES) {
            CP_WAIT1();
            __syncthreads();
            PREFETCH(s + 2);
        } else {
            CP_WAIT0();
            __syncthreads();
        }
        const uint32_t st = smem_base + (s % 3) * STAGE_BYTES;

#pragma unroll
        for (int ks = 0; ks < 4; ++ks) {
            uint32_t a[4][4], b[4][2];
            const int cA = 2 * ks + (lane >> 4);
#pragma unroll
            for (int mt = 0; mt < 4; ++mt) {
                int r = rA_base + mt * 16;
                uint32_t off = st + (uint32_t)(r * 128 + ((cA ^ (r & 7)) << 4));
                LDSM_X4(a[mt], off);
            }
            const int cB = 2 * ks + ((lane >> 3) & 1);
#pragma unroll
            for (int nt = 0; nt < 4; ++nt) {
                int r = rB_base + nt * 8;
                uint32_t off = st + ARR_BYTES + (uint32_t)(r * 128 + ((cB ^ (r & 7)) << 4));
                LDSM_X2(b[nt], off);
            }
#pragma unroll
            for (int mt = 0; mt < 4; ++mt)
#pragma unroll
                for (int nt = 0; nt < 4; ++nt)
                    mma16816(acc[mt][nt], a[mt], b[nt]);
        }
        __syncthreads();
    }
#undef PREFETCH

    // Epilogue: +bias, ReLU, store fp32
#pragma unroll
    for (int mt = 0; mt < 4; ++mt) {
        const int row0 = bn + wm * 64 + mt * 16 + (lane >> 2);
#pragma unroll
        for (int nt = 0; nt < 4; ++nt) {
            const int col0 = bh + wn * 32 + nt * 8 + (lane & 3) * 2;
            const float bb0 = bias[col0], bb1 = bias[col0 + 1];
            float2 v0, v1;
            v0.x = acc[mt][nt][0] + bb0; v0.x = v0.x > 0.0f ? v0.x : 0.0f;
            v0.y = acc[mt][nt][1] + bb1; v0.y = v0.y > 0.0f ? v0.y : 0.0f;
            v1.x = acc[mt][nt][2] + bb0; v1.x = v1.x > 0.0f ? v1.x : 0.0f;
            v1.y = acc[mt][nt][3] + bb1; v1.y = v1.y > 0.0f ? v1.y : 0.0f;
            *(float2*)&feat[(size_t)row0 * D_HIDDEN + col0]       = v0;
            *(float2*)&feat[(size_t)(row0 + 8) * D_HIDDEN + col0] = v1;
        }
    }
}

// ---------------- top-k: 1-pass linear histogram + margin classify ----------
__global__ __launch_bounds__(256)
void topk_kernel(float* __restrict__ feat)
{
    const int n   = blockIdx.x;
    const int tid = threadIdx.x;
    float* row = feat + (size_t)n * D_HIDDEN;

    __shared__ int hist[4096];
    __shared__ int s_part[256];
    __shared__ int s_bin;
    __shared__ int s_ndef, s_ncand;

    for (int i = tid; i < 4096; i += 256) hist[i] = 0;
    if (tid == 0) { s_bin = 0; s_ndef = 0; s_ncand = 0; }
    __syncthreads();

    for (int i = tid; i < D_HIDDEN; i += 256) {
        float v = row[i];
        if (v > 0.0f) {
            int b = (int)(v * 512.0f);
            if (b > 4095) b = 4095;
            atomicAdd(&hist[b], 1);
        }
    }
    __syncthreads();

    const int hi_b = 4095 - tid * 16;
    int part = 0;
#pragma unroll
    for (int j = 0; j < 16; ++j) part += hist[hi_b - j];
    s_part[tid] = part;
    __syncthreads();
    for (int off = 1; off < 256; off <<= 1) {
        int v2 = (tid >= off) ? s_part[tid - off] : 0;
        __syncthreads();
        s_part[tid] += v2;
        __syncthreads();
    }
    const int incl = s_part[tid];
    const int excl = incl - part;
    if (excl < TOPK && incl >= TOPK) {
        int cum = excl;
        for (int j = 0; j < 16; ++j) {
            cum += hist[hi_b - j];
            if (cum >= TOPK) { s_bin = hi_b - j; break; }
        }
    }
    __syncthreads();

    const float lo = (float)s_bin / 512.0f - MARGIN;
    const float hi = (float)(s_bin + 1) / 512.0f + MARGIN;

    for (int i = tid; i < D_HIDDEN; i += 256) {
        float v = row[i];
        if (v > hi) {
            int p = atomicAdd(&s_ndef, 1);
            g_topk_idx[n * TOPK + p] = i;
            g_topk_val[n * TOPK + p] = v;
        } else {
            if (v >= lo) {
                int q = atomicAdd(&s_ncand, 1);
                if (q < 64) { g_cand_idx[n * 64 + q] = i; g_cand_val[n * 64 + q] = v; }
            }
            row[i] = 0.0f;
        }
    }
    __syncthreads();
    if (tid == 0) {
        g_ndef[n]  = s_ndef;
        g_ncand[n] = s_ncand < 64 ? s_ncand : 64;
    }
}

// ---------------- rerank: exact fp64 scoring of boundary candidates ---------
__global__ __launch_bounds__(256)
void rerank_kernel(const float* __restrict__ x, const float* __restrict__ W_enc,
                   const float* __restrict__ b_enc, float* __restrict__ feat)
{
    __shared__ float  sx[D_IN];
    __shared__ double sred[256];
    __shared__ double s_exact[64];

    const int n   = blockIdx.x;
    const int tid = threadIdx.x;
    const int ndef  = g_ndef[n];
    const int ncand = g_ncand[n];
    const int need  = TOPK - ndef;
    float* row = feat + (size_t)n * D_HIDDEN;

    if (need <= 0) return;

    if (ncand <= need) {
        for (int c = tid; c < ncand; c += 256) {
            int idx = g_cand_idx[n * 64 + c];
            float v = g_cand_val[n * 64 + c];
            row[idx] = v;
            g_topk_idx[n * TOPK + ndef + c] = idx;
            g_topk_val[n * TOPK + ndef + c] = v;
        }
        return;
    }

    for (int i = tid * 4; i < D_IN; i += 1024)
        *(float4*)&sx[i] = *(const float4*)(x + (size_t)n * D_IN + i);
    __syncthreads();

    for (int c = 0; c < ncand; ++c) {
        const float* w = W_enc + (size_t)g_cand_idx[n * 64 + c] * D_IN;
        double acc = 0.0;
        for (int j = tid; j < D_IN; j += 256)
            acc += (double)sx[j] * (double)w[j];
        sred[tid] = acc;
        __syncthreads();
        for (int st = 128; st > 0; st >>= 1) {
            if (tid < st) sred[tid] += sred[tid + st];
            __syncthreads();
        }
        if (tid == 0) {
            double v = sred[0] + (double)b_enc[g_cand_idx[n * 64 + c]];
            s_exact[c] = v > 0.0 ? v : 0.0;
        }
        __syncthreads();
    }

    if (tid == 0) {
        bool used[64];
        for (int c = 0; c < ncand; ++c) used[c] = false;
        for (int r = 0; r < need; ++r) {
            int best = -1;
            for (int c = 0; c < ncand; ++c) {
                if (used[c]) continue;
                if (best < 0 || s_exact[c] > s_exact[best] ||
                    (s_exact[c] == s_exact[best] &&
                     g_cand_idx[n * 64 + c] < g_cand_idx[n * 64 + best]))
                    best = c;
            }
            used[best] = true;
            int idx = g_cand_idx[n * 64 + best];
            float v = g_cand_val[n * 64 + best];
            row[idx] = v;
            g_topk_idx[n * TOPK + ndef + r] = idx;
            g_topk_val[n * TOPK + ndef + r] = v;
        }
    }
}

// ---------------- transpose W_dec [d][h] -> g_wdecT fp16 [h][d] -------------
__global__ __launch_bounds__(256)
void transpose_kernel(const float* __restrict__ W)
{
    __shared__ float t[32][65];     // [h][d]
    const int h0 = blockIdx.x * 32;
    const int d0 = blockIdx.y * 64;
    const int tx = threadIdx.x;     // 0..31
    const int ty = threadIdx.y;     // 0..7

#pragma unroll
    for (int i = 0; i < 64; i += 8)
        t[tx][i + ty] = W[(size_t)(d0 + i + ty) * D_HIDDEN + h0 + tx];
    __syncthreads();
#pragma unroll
    for (int i = 0; i < 32; i += 8) {
        const int h = i + ty;
        __half2 hv = __half2{__float2half_rn(t[h][2 * tx]),
                             __float2half_rn(t[h][2 * tx + 1])};
        *(__half2*)(g_wdecT + (size_t)(h0 + h) * D_IN + d0 + 2 * tx) = hv;
    }
}

// ---------------- sparse decode (fp16 weights, fp32 accum) ------------------
__global__ __launch_bounds__(256)
void decode_kernel(float* __restrict__ recon, const float* __restrict__ b_dec)
{
    const int n   = blockIdx.x;
    const int tid = threadIdx.x;

    __shared__ int   s_idx[TOPK];
    __shared__ float s_val[TOPK];
    if (tid < TOPK) {
        s_idx[tid] = g_topk_idx[n * TOPK + tid];
        s_val[tid] = g_topk_val[n * TOPK + tid];
    }
    __syncthreads();

    float acc[16];
#pragma unroll
    for (int r = 0; r < 8; ++r) {
        float2 b = *(const float2*)(b_dec + 2 * (tid + r * 256));
        acc[2 * r] = b.x; acc[2 * r + 1] = b.y;
    }

    for (int j = 0; j < TOPK; ++j) {
        const __half2* wr = (const __half2*)(g_wdecT + (size_t)s_idx[j] * D_IN);
        const float v = s_val[j];
#pragma unroll
        for (int r = 0; r < 8; ++r) {
            float2 w = __half22float2(wr[tid + r * 256]);
            acc[2 * r]     += v * w.x;
            acc[2 * r + 1] += v * w.y;
        }
    }

    float* out = recon + (size_t)n * D_IN;
#pragma unroll
    for (int r = 0; r < 8; ++r) {
        float2 o; o.x = acc[2 * r]; o.y = acc[2 * r + 1];
        *(float2*)(out + 2 * (tid + r * 256)) = o;
    }
}

// ---------------- launch -----------------------------------------------------
extern "C" void kernel_launch(void* const* d_in, const int* in_sizes, int n_in,
                              void* d_out, int out_size)
{
    const float* x     = (const float*)d_in[0];
    const float* W_enc = (const float*)d_in[1];
    const float* b_enc = (const float*)d_in[2];
    const float* W_dec = (const float*)d_in[3];
    const float* b_dec = (const float*)d_in[4];

    float* recon = (float*)d_out;
    float* feat  = (float*)d_out + (size_t)N_TOKENS * D_IN;

    cudaFuncSetAttribute(encode_mma_kernel,
                         cudaFuncAttributeMaxDynamicSharedMemorySize, ENC_SMEM);

    split_x_kernel<<<(N_TOKENS * D_IN) / 1024, 256>>>(x);
    split_w_kernel<<<((size_t)D_HIDDEN * D_IN) / 1024, 256>>>(W_enc);
    transpose_kernel<<<dim3(D_HIDDEN / 32, D_IN / 64), dim3(32, 8)>>>(W_dec);

    encode_mma_kernel<<<dim3(N_TOKENS / 128, D_HIDDEN / 128), 256, ENC_SMEM>>>(b_enc, feat);

    topk_kernel<<<N_TOKENS, 256>>>(feat);
    rerank_kernel<<<N_TOKENS, 256>>>(x, W_enc, b_enc, feat);
    decode_kernel<<<N_TOKENS, 256>>>(recon, b_dec);
}

// round 11
// speedup vs baseline: 1.1152x; 1.0012x over previous
#include <cuda_runtime.h>
#include <cuda_fp16.h>
#include <cstdint>

#define N_TOKENS 4096
#define D_IN     4096
#define D_HIDDEN 32768
#define TOPK     64
#define MARGIN   5e-3f

// ---------------- device scratch (no allocations allowed) -------------------
__device__ __half g_x1[(size_t)N_TOKENS * D_IN];
__device__ __half g_w1[(size_t)D_HIDDEN * D_IN];
__device__ __half g_wdecT[(size_t)D_HIDDEN * D_IN];   // fp16 transposed decoder
__device__ int   g_topk_idx[N_TOKENS * TOPK];
__device__ float g_topk_val[N_TOKENS * TOPK];
__device__ int   g_cand_idx[N_TOKENS * 64];
__device__ float g_cand_val[N_TOKENS * 64];
__device__ int   g_ndef[N_TOKENS];
__device__ int   g_ncand[N_TOKENS];

// ---------------- helpers ----------------------------------------------------
__device__ __forceinline__ uint32_t smem_u32(const void* p) {
    uint32_t a;
    asm("{ .reg .u64 t; cvta.to.shared.u64 t, %1; cvt.u32.u64 %0, t; }" : "=r"(a) : "l"(p));
    return a;
}
__device__ __forceinline__ void cp16(uint32_t saddr, const void* gaddr) {
    asm volatile("cp.async.cg.shared.global [%0], [%1], 16;" :: "r"(saddr), "l"(gaddr));
}
#define CP_COMMIT()  asm volatile("cp.async.commit_group;" ::: "memory")
#define CP_WAIT0()   asm volatile("cp.async.wait_group 0;" ::: "memory")
#define CP_WAIT1()   asm volatile("cp.async.wait_group 1;" ::: "memory")

#define LDSM_X4(d, addr) \
    asm volatile("ldmatrix.sync.aligned.m8n8.x4.shared.b16 {%0,%1,%2,%3}, [%4];" \
        : "=r"((d)[0]), "=r"((d)[1]), "=r"((d)[2]), "=r"((d)[3]) : "r"(addr))
#define LDSM_X2(d, addr) \
    asm volatile("ldmatrix.sync.aligned.m8n8.x2.shared.b16 {%0,%1}, [%2];" \
        : "=r"((d)[0]), "=r"((d)[1]) : "r"(addr))

__device__ __forceinline__ void mma16816(float* d, const uint32_t* a, const uint32_t* b) {
    asm volatile("mma.sync.aligned.m16n8k16.row.col.f32.f16.f16.f32 "
        "{%0,%1,%2,%3}, {%4,%5,%6,%7}, {%8,%9}, {%0,%1,%2,%3};"
        : "+f"(d[0]), "+f"(d[1]), "+f"(d[2]), "+f"(d[3])
        : "r"(a[0]), "r"(a[1]), "r"(a[2]), "r"(a[3]), "r"(b[0]), "r"(b[1]));
}

// ---------------- convert kernels (fp32 -> fp16) ----------------------------
__global__ __launch_bounds__(256)
void split_x_kernel(const float* __restrict__ src)
{
    size_t i = ((size_t)blockIdx.x * 256 + threadIdx.x) * 4;
    if (i >= (size_t)N_TOKENS * D_IN) return;
    float4 v = *(const float4*)(src + i);
    *(__half2*)(g_x1 + i)     = __half2{__float2half_rn(v.x), __float2half_rn(v.y)};
    *(__half2*)(g_x1 + i + 2) = __half2{__float2half_rn(v.z), __float2half_rn(v.w)};
}

__global__ __launch_bounds__(256)
void split_w_kernel(const float* __restrict__ src)
{
    size_t i = ((size_t)blockIdx.x * 256 + threadIdx.x) * 4;
    if (i >= (size_t)D_HIDDEN * D_IN) return;
    float4 v = *(const float4*)(src + i);
    *(__half2*)(g_w1 + i)     = __half2{__float2half_rn(v.x), __float2half_rn(v.y)};
    *(__half2*)(g_w1 + i + 2) = __half2{__float2half_rn(v.z), __float2half_rn(v.w)};
}

// ---------------- encode: fp16 x*w GEMM on mma.sync (R7 config, verbatim) ---
// CTA tile 128(tok) x 128(hid), BK=64, 8 warps 2x4, warp tile 64x32.
// SMEM stage: X|W (2 x 16KB, XOR chunk swizzle), 3-stage cp.async pipeline,
// 96KB smem -> 2 CTAs/SM (launch_bounds caps regs at 128).
#define EBK 64
#define ARR_BYTES 16384
#define STAGE_BYTES (2 * ARR_BYTES)      // 32KB
#define ENC_SMEM (3 * STAGE_BYTES)       // 96KB
#define N_STAGES (D_IN / EBK)            // 64

__global__ __launch_bounds__(256, 2)
void encode_mma_kernel(const float* __restrict__ bias, float* __restrict__ feat)
{
    extern __shared__ __align__(128) char smem[];
    const int tid  = threadIdx.x;
    const int wid  = tid >> 5;
    const int lane = tid & 31;
    const int wm   = wid >> 2;       // 0..1
    const int wn   = wid & 3;        // 0..3
    const int bn   = blockIdx.x * 128;   // token tile (fastest -> B tile L2-hot)
    const int bh   = blockIdx.y * 128;   // hidden tile
    const uint32_t smem_base = smem_u32(smem);

    float acc[4][4][4];
#pragma unroll
    for (int mt = 0; mt < 4; ++mt)
#pragma unroll
        for (int nt = 0; nt < 4; ++nt)
#pragma unroll
            for (int q = 0; q < 4; ++q) acc[mt][nt][q] = 0.0f;

#define PREFETCH(s) do {                                                          \
    const int _k0 = (s) * EBK;                                                    \
    const uint32_t _st = smem_base + ((s) % 3) * STAGE_BYTES;                     \
    _Pragma("unroll")                                                             \
    for (int _l = 0; _l < 4; ++_l) {                                              \
        int _id = _l * 256 + tid;                                                 \
        int _r = _id >> 3, _c = _id & 7;                                          \
        uint32_t _sw = (uint32_t)(_r * 128 + ((_c ^ (_r & 7)) << 4));             \
        size_t _ga = (size_t)(bn + _r) * D_IN + _k0 + _c * 8;                     \
        size_t _gb = (size_t)(bh + _r) * D_IN + _k0 + _c * 8;                     \
        cp16(_st + 0 * ARR_BYTES + _sw, g_x1 + _ga);                              \
        cp16(_st + 1 * ARR_BYTES + _sw, g_w1 + _gb);                              \
    }                                                                             \
    CP_COMMIT();                                                                  \
} while (0)

    PREFETCH(0);
    PREFETCH(1);

    const int rA_base = wm * 64 + (lane & 15);
    const int rB_base = wn * 32 + (lane & 7);

    for (int s = 0; s < N_STAGES; ++s) {
        if (s + 2 < N_STAGES) {
            CP_WAIT1();
            __syncthreads();
            PREFETCH(s + 2);
        } else {
            CP_WAIT0();
            __syncthreads();
        }
        const uint32_t st = smem_base + (s % 3) * STAGE_BYTES;

#pragma unroll
        for (int ks = 0; ks < 4; ++ks) {
            uint32_t a[4][4], b[4][2];
            const int cA = 2 * ks + (lane >> 4);
#pragma unroll
            for (int mt = 0; mt < 4; ++mt) {
                int r = rA_base + mt * 16;
                uint32_t off = st + (uint32_t)(r * 128 + ((cA ^ (r & 7)) << 4));
                LDSM_X4(a[mt], off);
            }
            const int cB = 2 * ks + ((lane >> 3) & 1);
#pragma unroll
            for (int nt = 0; nt < 4; ++nt) {
                int r = rB_base + nt * 8;
                uint32_t off = st + ARR_BYTES + (uint32_t)(r * 128 + ((cB ^ (r & 7)) << 4));
                LDSM_X2(b[nt], off);
            }
#pragma unroll
            for (int mt = 0; mt < 4; ++mt)
#pragma unroll
                for (int nt = 0; nt < 4; ++nt)
                    mma16816(acc[mt][nt], a[mt], b[nt]);
        }
        __syncthreads();
    }
#undef PREFETCH

    // Epilogue: +bias, ReLU, store fp32
#pragma unroll
    for (int mt = 0; mt < 4; ++mt) {
        const int row0 = bn + wm * 64 + mt * 16 + (lane >> 2);
#pragma unroll
        for (int nt = 0; nt < 4; ++nt) {
            const int col0 = bh + wn * 32 + nt * 8 + (lane & 3) * 2;
            const float bb0 = bias[col0], bb1 = bias[col0 + 1];
            float2 v0, v1;
            v0.x = acc[mt][nt][0] + bb0; v0.x = v0.x > 0.0f ? v0.x : 0.0f;
            v0.y = acc[mt][nt][1] + bb1; v0.y = v0.y > 0.0f ? v0.y : 0.0f;
            v1.x = acc[mt][nt][2] + bb0; v1.x = v1.x > 0.0f ? v1.x : 0.0f;
            v1.y = acc[mt][nt][3] + bb1; v1.y = v1.y > 0.0f ? v1.y : 0.0f;
            *(float2*)&feat[(size_t)row0 * D_HIDDEN + col0]       = v0;
            *(float2*)&feat[(size_t)(row0 + 8) * D_HIDDEN + col0] = v1;
        }
    }
}

// ---------------- top-k: 1-pass linear histogram + margin classify ----------
__global__ __launch_bounds__(256)
void topk_kernel(float* __restrict__ feat)
{
    const int n   = blockIdx.x;
    const int tid = threadIdx.x;
    float* row = feat + (size_t)n * D_HIDDEN;

    __shared__ int hist[4096];
    __shared__ int s_part[256];
    __shared__ int s_bin;
    __shared__ int s_ndef, s_ncand;

    for (int i = tid; i < 4096; i += 256) hist[i] = 0;
    if (tid == 0) { s_bin = 0; s_ndef = 0; s_ncand = 0; }
    __syncthreads();

    for (int i = tid; i < D_HIDDEN; i += 256) {
        float v = row[i];
        if (v > 0.0f) {
            int b = (int)(v * 512.0f);
            if (b > 4095) b = 4095;
            atomicAdd(&hist[b], 1);
        }
    }
    __syncthreads();

    const int hi_b = 4095 - tid * 16;
    int part = 0;
#pragma unroll
    for (int j = 0; j < 16; ++j) part += hist[hi_b - j];
    s_part[tid] = part;
    __syncthreads();
    for (int off = 1; off < 256; off <<= 1) {
        int v2 = (tid >= off) ? s_part[tid - off] : 0;
        __syncthreads();
        s_part[tid] += v2;
        __syncthreads();
    }
    const int incl = s_part[tid];
    const int excl = incl - part;
    if (excl < TOPK && incl >= TOPK) {
        int cum = excl;
        for (int j = 0; j < 16; ++j) {
            cum += hist[hi_b - j];
            if (cum >= TOPK) { s_bin = hi_b - j; break; }
        }
    }
    __syncthreads();

    const float lo = (float)s_bin / 512.0f - MARGIN;
    const float hi = (float)(s_bin + 1) / 512.0f + MARGIN;

    for (int i = tid; i < D_HIDDEN; i += 256) {
        float v = row[i];
        if (v > hi) {
            int p = atomicAdd(&s_ndef, 1);
            g_topk_idx[n * TOPK + p] = i;
            g_topk_val[n * TOPK + p] = v;
        } else {
            if (v >= lo) {
                int q = atomicAdd(&s_ncand, 1);
                if (q < 64) { g_cand_idx[n * 64 + q] = i; g_cand_val[n * 64 + q] = v; }
            }
            row[i] = 0.0f;
        }
    }
    __syncthreads();
    if (tid == 0) {
        g_ndef[n]  = s_ndef;
        g_ncand[n] = s_ncand < 64 ? s_ncand : 64;
    }
}

// ---------------- rerank: exact fp64 scoring of boundary candidates ---------
__global__ __launch_bounds__(256)
void rerank_kernel(const float* __restrict__ x, const float* __restrict__ W_enc,
                   const float* __restrict__ b_enc, float* __restrict__ feat)
{
    __shared__ float  sx[D_IN];
    __shared__ double sred[256];
    __shared__ double s_exact[64];

    const int n   = blockIdx.x;
    const int tid = threadIdx.x;
    const int ndef  = g_ndef[n];
    const int ncand = g_ncand[n];
    const int need  = TOPK - ndef;
    float* row = feat + (size_t)n * D_HIDDEN;

    if (need <= 0) return;

    if (ncand <= need) {
        for (int c = tid; c < ncand; c += 256) {
            int idx = g_cand_idx[n * 64 + c];
            float v = g_cand_val[n * 64 + c];
            row[idx] = v;
            g_topk_idx[n * TOPK + ndef + c] = idx;
            g_topk_val[n * TOPK + ndef + c] = v;
        }
        return;
    }

    for (int i = tid * 4; i < D_IN; i += 1024)
        *(float4*)&sx[i] = *(const float4*)(x + (size_t)n * D_IN + i);
    __syncthreads();

    for (int c = 0; c < ncand; ++c) {
        const float* w = W_enc + (size_t)g_cand_idx[n * 64 + c] * D_IN;
        double acc = 0.0;
        for (int j = tid; j < D_IN; j += 256)
            acc += (double)sx[j] * (double)w[j];
        sred[tid] = acc;
        __syncthreads();
        for (int st = 128; st > 0; st >>= 1) {
            if (tid < st) sred[tid] += sred[tid + st];
            __syncthreads();
        }
        if (tid == 0) {
            double v = sred[0] + (double)b_enc[g_cand_idx[n * 64 + c]];
            s_exact[c] = v > 0.0 ? v : 0.0;
        }
        __syncthreads();
    }

    if (tid == 0) {
        bool used[64];
        for (int c = 0; c < ncand; ++c) used[c] = false;
        for (int r = 0; r < need; ++r) {
            int best = -1;
            for (int c = 0; c < ncand; ++c) {
                if (used[c]) continue;
                if (best < 0 || s_exact[c] > s_exact[best] ||
                    (s_exact[c] == s_exact[best] &&
                     g_cand_idx[n * 64 + c] < g_cand_idx[n * 64 + best]))
                    best = c;
            }
            used[best] = true;
            int idx = g_cand_idx[n * 64 + best];
            float v = g_cand_val[n * 64 + best];
            row[idx] = v;
            g_topk_idx[n * TOPK + ndef + r] = idx;
            g_topk_val[n * TOPK + ndef + r] = v;
        }
    }
}

// ---------------- transpose W_dec [d][h] -> g_wdecT fp16 [h][d] -------------
__global__ __launch_bounds__(256)
void transpose_kernel(const float* __restrict__ W)
{
    __shared__ float t[32][65];     // [h][d]
    const int h0 = blockIdx.x * 32;
    const int d0 = blockIdx.y * 64;
    const int tx = threadIdx.x;     // 0..31
    const int ty = threadIdx.y;     // 0..7

#pragma unroll
    for (int i = 0; i < 64; i += 8)
        t[tx][i + ty] = W[(size_t)(d0 + i + ty) * D_HIDDEN + h0 + tx];
    __syncthreads();
#pragma unroll
    for (int i = 0; i < 32; i += 8) {
        const int h = i + ty;
        __half2 hv = __half2{__float2half_rn(t[h][2 * tx]),
                             __float2half_rn(t[h][2 * tx + 1])};
        *(__half2*)(g_wdecT + (size_t)(h0 + h) * D_IN + d0 + 2 * tx) = hv;
    }
}

// ---------------- sparse decode (fp16 weights, fp32 accum) ------------------
__global__ __launch_bounds__(256)
void decode_kernel(float* __restrict__ recon, const float* __restrict__ b_dec)
{
    const int n   = blockIdx.x;
    const int tid = threadIdx.x;

    __shared__ int   s_idx[TOPK];
    __shared__ float s_val[TOPK];
    if (tid < TOPK) {
        s_idx[tid] = g_topk_idx[n * TOPK + tid];
        s_val[tid] = g_topk_val[n * TOPK + tid];
    }
    __syncthreads();

    float acc[16];
#pragma unroll
    for (int r = 0; r < 8; ++r) {
        float2 b = *(const float2*)(b_dec + 2 * (tid + r * 256));
        acc[2 * r] = b.x; acc[2 * r + 1] = b.y;
    }

    for (int j = 0; j < TOPK; ++j) {
        const __half2* wr = (const __half2*)(g_wdecT + (size_t)s_idx[j] * D_IN);
        const float v = s_val[j];
#pragma unroll
        for (int r = 0; r < 8; ++r) {
            float2 w = __half22float2(wr[tid + r * 256]);
            acc[2 * r]     += v * w.x;
            acc[2 * r + 1] += v * w.y;
        }
    }

    float* out = recon + (size_t)n * D_IN;
#pragma unroll
    for (int r = 0; r < 8; ++r) {
        float2 o; o.x = acc[2 * r]; o.y = acc[2 * r + 1];
        *(float2*)(out + 2 * (tid + r * 256)) = o;
    }
}

// ---------------- launch -----------------------------------------------------
extern "C" void kernel_launch(void* const* d_in, const int* in_sizes, int n_in,
                              void* d_out, int out_size)
{
    const float* x     = (const float*)d_in[0];
    const float* W_enc = (const float*)d_in[1];
    const float* b_enc = (const float*)d_in[2];
    const float* W_dec = (const float*)d_in[3];
    const float* b_dec = (const float*)d_in[4];

    float* recon = (float*)d_out;
    float* feat  = (float*)d_out + (size_t)N_TOKENS * D_IN;

    cudaFuncSetAttribute(encode_mma_kernel,
                         cudaFuncAttributeMaxDynamicSharedMemorySize, ENC_SMEM);

    split_x_kernel<<<(N_TOKENS * D_IN) / 1024, 256>>>(x);
    split_w_kernel<<<((size_t)D_HIDDEN * D_IN) / 1024, 256>>>(W_enc);
    transpose_kernel<<<dim3(D_HIDDEN / 32, D_IN / 64), dim3(32, 8)>>>(W_dec);

    encode_mma_kernel<<<dim3(N_TOKENS / 128, D_HIDDEN / 128), 256, ENC_SMEM>>>(b_enc, feat);

    topk_kernel<<<N_TOKENS, 256>>>(feat);
    rerank_kernel<<<N_TOKENS, 256>>>(x, W_enc, b_enc, feat);
    decode_kernel<<<N_TOKENS, 256>>>(recon, b_dec);
}

// round 12
// speedup vs baseline: 1.1158x; 1.0006x over previous
#include <cuda_runtime.h>
#include <cuda_fp16.h>
#include <cstdint>

#define N_TOKENS 4096
#define D_IN     4096
#define D_HIDDEN 32768
#define TOPK     64
#define MARGIN   5e-3f

// ---------------- device scratch (no allocations allowed) -------------------
__device__ __half g_x1[(size_t)N_TOKENS * D_IN];
__device__ __half g_w1[(size_t)D_HIDDEN * D_IN];
__device__ __half g_wdecT[(size_t)D_HIDDEN * D_IN];   // fp16 transposed decoder
__device__ int   g_topk_idx[N_TOKENS * TOPK];
__device__ float g_topk_val[N_TOKENS * TOPK];
__device__ int   g_cand_idx[N_TOKENS * 64];
__device__ float g_cand_val[N_TOKENS * 64];
__device__ int   g_ndef[N_TOKENS];
__device__ int   g_ncand[N_TOKENS];

// ---------------- helpers ----------------------------------------------------
__device__ __forceinline__ uint32_t smem_u32(const void* p) {
    uint32_t a;
    asm("{ .reg .u64 t; cvta.to.shared.u64 t, %1; cvt.u32.u64 %0, t; }" : "=r"(a) : "l"(p));
    return a;
}
__device__ __forceinline__ void cp16(uint32_t saddr, const void* gaddr) {
    asm volatile("cp.async.cg.shared.global [%0], [%1], 16;" :: "r"(saddr), "l"(gaddr));
}
#define CP_COMMIT()  asm volatile("cp.async.commit_group;" ::: "memory")
#define CP_WAIT0()   asm volatile("cp.async.wait_group 0;" ::: "memory")
#define CP_WAIT1()   asm volatile("cp.async.wait_group 1;" ::: "memory")

#define LDSM_X4(d, addr) \
    asm volatile("ldmatrix.sync.aligned.m8n8.x4.shared.b16 {%0,%1,%2,%3}, [%4];" \
        : "=r"((d)[0]), "=r"((d)[1]), "=r"((d)[2]), "=r"((d)[3]) : "r"(addr))
#define LDSM_X2(d, addr) \
    asm volatile("ldmatrix.sync.aligned.m8n8.x2.shared.b16 {%0,%1}, [%2];" \
        : "=r"((d)[0]), "=r"((d)[1]) : "r"(addr))

__device__ __forceinline__ void mma16816(float* d, const uint32_t* a, const uint32_t* b) {
    asm volatile("mma.sync.aligned.m16n8k16.row.col.f32.f16.f16.f32 "
        "{%0,%1,%2,%3}, {%4,%5,%6,%7}, {%8,%9}, {%0,%1,%2,%3};"
        : "+f"(d[0]), "+f"(d[1]), "+f"(d[2]), "+f"(d[3])
        : "r"(a[0]), "r"(a[1]), "r"(a[2]), "r"(a[3]), "r"(b[0]), "r"(b[1]));
}

// ---------------- convert kernels (fp32 -> fp16) ----------------------------
__global__ __launch_bounds__(256)
void split_x_kernel(const float* __restrict__ src)
{
    size_t i = ((size_t)blockIdx.x * 256 + threadIdx.x) * 4;
    if (i >= (size_t)N_TOKENS * D_IN) return;
    float4 v = *(const float4*)(src + i);
    *(__half2*)(g_x1 + i)     = __half2{__float2half_rn(v.x), __float2half_rn(v.y)};
    *(__half2*)(g_x1 + i + 2) = __half2{__float2half_rn(v.z), __float2half_rn(v.w)};
}

__global__ __launch_bounds__(256)
void split_w_kernel(const float* __restrict__ src)
{
    size_t i = ((size_t)blockIdx.x * 256 + threadIdx.x) * 4;
    if (i >= (size_t)D_HIDDEN * D_IN) return;
    float4 v = *(const float4*)(src + i);
    *(__half2*)(g_w1 + i)     = __half2{__float2half_rn(v.x), __float2half_rn(v.y)};
    *(__half2*)(g_w1 + i + 2) = __half2{__float2half_rn(v.z), __float2half_rn(v.w)};
}

// ---------------- encode: fp16 x*w GEMM on mma.sync (R7 config, verbatim) ---
// CTA tile 128(tok) x 128(hid), BK=64, 8 warps 2x4, warp tile 64x32.
// SMEM stage: X|W (2 x 16KB, XOR chunk swizzle), 3-stage cp.async pipeline,
// 96KB smem -> 2 CTAs/SM (launch_bounds caps regs at 128).
#define EBK 64
#define ARR_BYTES 16384
#define STAGE_BYTES (2 * ARR_BYTES)      // 32KB
#define ENC_SMEM (3 * STAGE_BYTES)       // 96KB
#define N_STAGES (D_IN / EBK)            // 64

__global__ __launch_bounds__(256, 2)
void encode_mma_kernel(const float* __restrict__ bias, float* __restrict__ feat)
{
    extern __shared__ __align__(128) char smem[];
    const int tid  = threadIdx.x;
    const int wid  = tid >> 5;
    const int lane = tid & 31;
    const int wm   = wid >> 2;       // 0..1
    const int wn   = wid & 3;        // 0..3
    const int bn   = blockIdx.x * 128;   // token tile (fastest -> B tile L2-hot)
    const int bh   = blockIdx.y * 128;   // hidden tile
    const uint32_t smem_base = smem_u32(smem);

    float acc[4][4][4];
#pragma unroll
    for (int mt = 0; mt < 4; ++mt)
#pragma unroll
        for (int nt = 0; nt < 4; ++nt)
#pragma unroll
            for (int q = 0; q < 4; ++q) acc[mt][nt][q] = 0.0f;

#define PREFETCH(s) do {                                                          \
    const int _k0 = (s) * EBK;                                                    \
    const uint32_t _st = smem_base + ((s) % 3) * STAGE_BYTES;                     \
    _Pragma("unroll")                                                             \
    for (int _l = 0; _l < 4; ++_l) {                                              \
        int _id = _l * 256 + tid;                                                 \
        int _r = _id >> 3, _c = _id & 7;                                          \
        uint32_t _sw = (uint32_t)(_r * 128 + ((_c ^ (_r & 7)) << 4));             \
        size_t _ga = (size_t)(bn + _r) * D_IN + _k0 + _c * 8;                     \
        size_t _gb = (size_t)(bh + _r) * D_IN + _k0 + _c * 8;                     \
        cp16(_st + 0 * ARR_BYTES + _sw, g_x1 + _ga);                              \
        cp16(_st + 1 * ARR_BYTES + _sw, g_w1 + _gb);                              \
    }                                                                             \
    CP_COMMIT();                                                                  \
} while (0)

    PREFETCH(0);
    PREFETCH(1);

    const int rA_base = wm * 64 + (lane & 15);
    const int rB_base = wn * 32 + (lane & 7);

    for (int s = 0; s < N_STAGES; ++s) {
        if (s + 2 < N_STAGES) {
            CP_WAIT1();
            __syncthreads();
            PREFETCH(s + 2);
        } else {
            CP_WAIT0();
            __syncthreads();
        }
        const uint32_t st = smem_base + (s % 3) * STAGE_BYTES;

#pragma unroll
        for (int ks = 0; ks < 4; ++ks) {
            uint32_t a[4][4], b[4][2];
            const int cA = 2 * ks + (lane >> 4);
#pragma unroll
            for (int mt = 0; mt < 4; ++mt) {
                int r = rA_base + mt * 16;
                uint32_t off = st + (uint32_t)(r * 128 + ((cA ^ (r & 7)) << 4));
                LDSM_X4(a[mt], off);
            }
            const int cB = 2 * ks + ((lane >> 3) & 1);
#pragma unroll
            for (int nt = 0; nt < 4; ++nt) {
                int r = rB_base + nt * 8;
                uint32_t off = st + ARR_BYTES + (uint32_t)(r * 128 + ((cB ^ (r & 7)) << 4));
                LDSM_X2(b[nt], off);
            }
#pragma unroll
            for (int mt = 0; mt < 4; ++mt)
#pragma unroll
                for (int nt = 0; nt < 4; ++nt)
                    mma16816(acc[mt][nt], a[mt], b[nt]);
        }
        __syncthreads();
    }
#undef PREFETCH

    // Epilogue: +bias, ReLU, store fp32
#pragma unroll
    for (int mt = 0; mt < 4; ++mt) {
        const int row0 = bn + wm * 64 + mt * 16 + (lane >> 2);
#pragma unroll
        for (int nt = 0; nt < 4; ++nt) {
            const int col0 = bh + wn * 32 + nt * 8 + (lane & 3) * 2;
            const float bb0 = bias[col0], bb1 = bias[col0 + 1];
            float2 v0, v1;
            v0.x = acc[mt][nt][0] + bb0; v0.x = v0.x > 0.0f ? v0.x : 0.0f;
            v0.y = acc[mt][nt][1] + bb1; v0.y = v0.y > 0.0f ? v0.y : 0.0f;
            v1.x = acc[mt][nt][2] + bb0; v1.x = v1.x > 0.0f ? v1.x : 0.0f;
            v1.y = acc[mt][nt][3] + bb1; v1.y = v1.y > 0.0f ? v1.y : 0.0f;
            *(float2*)&feat[(size_t)row0 * D_HIDDEN + col0]       = v0;
            *(float2*)&feat[(size_t)(row0 + 8) * D_HIDDEN + col0] = v1;
        }
    }
}

// ---------------- top-k: 1-pass linear histogram + margin classify ----------
__global__ __launch_bounds__(256)
void topk_kernel(float* __restrict__ feat)
{
    const int n   = blockIdx.x;
    const int tid = threadIdx.x;
    float* row = feat + (size_t)n * D_HIDDEN;

    __shared__ int hist[4096];
    __shared__ int s_part[256];
    __shared__ int s_bin;
    __shared__ int s_ndef, s_ncand;

    for (int i = tid; i < 4096; i += 256) hist[i] = 0;
    if (tid == 0) { s_bin = 0; s_ndef = 0; s_ncand = 0; }
    __syncthreads();

    for (int i = tid; i < D_HIDDEN; i += 256) {
        float v = row[i];
        if (v > 0.0f) {
            int b = (int)(v * 512.0f);
            if (b > 4095) b = 4095;
            atomicAdd(&hist[b], 1);
        }
    }
    __syncthreads();

    const int hi_b = 4095 - tid * 16;
    int part = 0;
#pragma unroll
    for (int j = 0; j < 16; ++j) part += hist[hi_b - j];
    s_part[tid] = part;
    __syncthreads();
    for (int off = 1; off < 256; off <<= 1) {
        int v2 = (tid >= off) ? s_part[tid - off] : 0;
        __syncthreads();
        s_part[tid] += v2;
        __syncthreads();
    }
    const int incl = s_part[tid];
    const int excl = incl - part;
    if (excl < TOPK && incl >= TOPK) {
        int cum = excl;
        for (int j = 0; j < 16; ++j) {
            cum += hist[hi_b - j];
            if (cum >= TOPK) { s_bin = hi_b - j; break; }
        }
    }
    __syncthreads();

    const float lo = (float)s_bin / 512.0f - MARGIN;
    const float hi = (float)(s_bin + 1) / 512.0f + MARGIN;

    for (int i = tid; i < D_HIDDEN; i += 256) {
        float v = row[i];
        if (v > hi) {
            int p = atomicAdd(&s_ndef, 1);
            g_topk_idx[n * TOPK + p] = i;
            g_topk_val[n * TOPK + p] = v;
        } else {
            if (v >= lo) {
                int q = atomicAdd(&s_ncand, 1);
                if (q < 64) { g_cand_idx[n * 64 + q] = i; g_cand_val[n * 64 + q] = v; }
            }
            row[i] = 0.0f;
        }
    }
    __syncthreads();
    if (tid == 0) {
        g_ndef[n]  = s_ndef;
        g_ncand[n] = s_ncand < 64 ? s_ncand : 64;
    }
}

// ---------------- rerank: exact fp64 scoring of boundary candidates ---------
__global__ __launch_bounds__(256)
void rerank_kernel(const float* __restrict__ x, const float* __restrict__ W_enc,
                   const float* __restrict__ b_enc, float* __restrict__ feat)
{
    __shared__ float  sx[D_IN];
    __shared__ double sred[256];
    __shared__ double s_exact[64];

    const int n   = blockIdx.x;
    const int tid = threadIdx.x;
    const int ndef  = g_ndef[n];
    const int ncand = g_ncand[n];
    const int need  = TOPK - ndef;
    float* row = feat + (size_t)n * D_HIDDEN;

    if (need <= 0) return;

    if (ncand <= need) {
        for (int c = tid; c < ncand; c += 256) {
            int idx = g_cand_idx[n * 64 + c];
            float v = g_cand_val[n * 64 + c];
            row[idx] = v;
            g_topk_idx[n * TOPK + ndef + c] = idx;
            g_topk_val[n * TOPK + ndef + c] = v;
        }
        return;
    }

    for (int i = tid * 4; i < D_IN; i += 1024)
        *(float4*)&sx[i] = *(const float4*)(x + (size_t)n * D_IN + i);
    __syncthreads();

    for (int c = 0; c < ncand; ++c) {
        const float* w = W_enc + (size_t)g_cand_idx[n * 64 + c] * D_IN;
        double acc = 0.0;
        for (int j = tid; j < D_IN; j += 256)
            acc += (double)sx[j] * (double)w[j];
        sred[tid] = acc;
        __syncthreads();
        for (int st = 128; st > 0; st >>= 1) {
            if (tid < st) sred[tid] += sred[tid + st];
            __syncthreads();
        }
        if (tid == 0) {
            double v = sred[0] + (double)b_enc[g_cand_idx[n * 64 + c]];
            s_exact[c] = v > 0.0 ? v : 0.0;
        }
        __syncthreads();
    }

    if (tid == 0) {
        bool used[64];
        for (int c = 0; c < ncand; ++c) used[c] = false;
        for (int r = 0; r < need; ++r) {
            int best = -1;
            for (int c = 0; c < ncand; ++c) {
                if (used[c]) continue;
                if (best < 0 || s_exact[c] > s_exact[best] ||
                    (s_exact[c] == s_exact[best] &&
                     g_cand_idx[n * 64 + c] < g_cand_idx[n * 64 + best]))
                    best = c;
            }
            used[best] = true;
            int idx = g_cand_idx[n * 64 + best];
            float v = g_cand_val[n * 64 + best];
            row[idx] = v;
            g_topk_idx[n * TOPK + ndef + r] = idx;
            g_topk_val[n * TOPK + ndef + r] = v;
        }
    }
}

// ---------------- transpose W_dec [d][h] -> g_wdecT fp16 [h][d] -------------
__global__ __launch_bounds__(256)
void transpose_kernel(const float* __restrict__ W)
{
    __shared__ float t[32][65];     // [h][d]
    const int h0 = blockIdx.x * 32;
    const int d0 = blockIdx.y * 64;
    const int tx = threadIdx.x;     // 0..31
    const int ty = threadIdx.y;     // 0..7

#pragma unroll
    for (int i = 0; i < 64; i += 8)
        t[tx][i + ty] = W[(size_t)(d0 + i + ty) * D_HIDDEN + h0 + tx];
    __syncthreads();
#pragma unroll
    for (int i = 0; i < 32; i += 8) {
        const int h = i + ty;
        __half2 hv = __half2{__float2half_rn(t[h][2 * tx]),
                             __float2half_rn(t[h][2 * tx + 1])};
        *(__half2*)(g_wdecT + (size_t)(h0 + h) * D_IN + d0 + 2 * tx) = hv;
    }
}

// ---------------- sparse decode (fp16 weights, fp32 accum) ------------------
__global__ __launch_bounds__(256)
void decode_kernel(float* __restrict__ recon, const float* __restrict__ b_dec)
{
    const int n   = blockIdx.x;
    const int tid = threadIdx.x;

    __shared__ int   s_idx[TOPK];
    __shared__ float s_val[TOPK];
    if (tid < TOPK) {
        s_idx[tid] = g_topk_idx[n * TOPK + tid];
        s_val[tid] = g_topk_val[n * TOPK + tid];
    }
    __syncthreads();

    float acc[16];
#pragma unroll
    for (int r = 0; r < 8; ++r) {
        float2 b = *(const float2*)(b_dec + 2 * (tid + r * 256));
        acc[2 * r] = b.x; acc[2 * r + 1] = b.y;
    }

    for (int j = 0; j < TOPK; ++j) {
        const __half2* wr = (const __half2*)(g_wdecT + (size_t)s_idx[j] * D_IN);
        const float v = s_val[j];
#pragma unroll
        for (int r = 0; r < 8; ++r) {
            float2 w = __half22float2(wr[tid + r * 256]);
            acc[2 * r]     += v * w.x;
            acc[2 * r + 1] += v * w.y;
        }
    }

    float* out = recon + (size_t)n * D_IN;
#pragma unroll
    for (int r = 0; r < 8; ++r) {
        float2 o; o.x = acc[2 * r]; o.y = acc[2 * r + 1];
        *(float2*)(out + 2 * (tid + r * 256)) = o;
    }
}

// ---------------- launch -----------------------------------------------------
extern "C" void kernel_launch(void* const* d_in, const int* in_sizes, int n_in,
                              void* d_out, int out_size)
{
    const float* x     = (const float*)d_in[0];
    const float* W_enc = (const float*)d_in[1];
    const float* b_enc = (const float*)d_in[2];
    const float* W_dec = (const float*)d_in[3];
    const float* b_dec = (const float*)d_in[4];

    float* recon = (float*)d_out;
    float* feat  = (float*)d_out + (size_t)N_TOKENS * D_IN;

    cudaFuncSetAttribute(encode_mma_kernel,
                         cudaFuncAttributeMaxDynamicSharedMemorySize, ENC_SMEM);

    split_x_kernel<<<(N_TOKENS * D_IN) / 1024, 256>>>(x);
    split_w_kernel<<<((size_t)D_HIDDEN * D_IN) / 1024, 256>>>(W_enc);
    transpose_kernel<<<dim3(D_HIDDEN / 32, D_IN / 64), dim3(32, 8)>>>(W_dec);

    encode_mma_kernel<<<dim3(N_TOKENS / 128, D_HIDDEN / 128), 256, ENC_SMEM>>>(b_enc, feat);

    topk_kernel<<<N_TOKENS, 256>>>(feat);
    rerank_kernel<<<N_TOKENS, 256>>>(x, W_enc, b_enc, feat);
    decode_kernel<<<N_TOKENS, 256>>>(recon, b_dec);
}

// round 13
// speedup vs baseline: 1.1161x; 1.0003x over previous
#include <cuda_runtime.h>
#include <cuda_fp16.h>
#include <cstdint>

#define N_TOKENS 4096
#define D_IN     4096
#define D_HIDDEN 32768
#define TOPK     64
#define MARGIN   5e-3f

// ---------------- device scratch (no allocations allowed) -------------------
__device__ __half g_x1[(size_t)N_TOKENS * D_IN];
__device__ __half g_w1[(size_t)D_HIDDEN * D_IN];
__device__ __half g_wdecT[(size_t)D_HIDDEN * D_IN];   // fp16 transposed decoder
__device__ int   g_topk_idx[N_TOKENS * TOPK];
__device__ float g_topk_val[N_TOKENS * TOPK];
__device__ int   g_cand_idx[N_TOKENS * 64];
__device__ float g_cand_val[N_TOKENS * 64];
__device__ int   g_ndef[N_TOKENS];
__device__ int   g_ncand[N_TOKENS];

// ---------------- helpers ----------------------------------------------------
__device__ __forceinline__ uint32_t smem_u32(const void* p) {
    uint32_t a;
    asm("{ .reg .u64 t; cvta.to.shared.u64 t, %1; cvt.u32.u64 %0, t; }" : "=r"(a) : "l"(p));
    return a;
}
__device__ __forceinline__ void cp16(uint32_t saddr, const void* gaddr) {
    asm volatile("cp.async.cg.shared.global [%0], [%1], 16;" :: "r"(saddr), "l"(gaddr));
}
#define CP_COMMIT()  asm volatile("cp.async.commit_group;" ::: "memory")
#define CP_WAIT0()   asm volatile("cp.async.wait_group 0;" ::: "memory")
#define CP_WAIT1()   asm volatile("cp.async.wait_group 1;" ::: "memory")

#define LDSM_X4(d, addr) \
    asm volatile("ldmatrix.sync.aligned.m8n8.x4.shared.b16 {%0,%1,%2,%3}, [%4];" \
        : "=r"((d)[0]), "=r"((d)[1]), "=r"((d)[2]), "=r"((d)[3]) : "r"(addr))
#define LDSM_X2(d, addr) \
    asm volatile("ldmatrix.sync.aligned.m8n8.x2.shared.b16 {%0,%1}, [%2];" \
        : "=r"((d)[0]), "=r"((d)[1]) : "r"(addr))

__device__ __forceinline__ void mma16816(float* d, const uint32_t* a, const uint32_t* b) {
    asm volatile("mma.sync.aligned.m16n8k16.row.col.f32.f16.f16.f32 "
        "{%0,%1,%2,%3}, {%4,%5,%6,%7}, {%8,%9}, {%0,%1,%2,%3};"
        : "+f"(d[0]), "+f"(d[1]), "+f"(d[2]), "+f"(d[3])
        : "r"(a[0]), "r"(a[1]), "r"(a[2]), "r"(a[3]), "r"(b[0]), "r"(b[1]));
}

// ---------------- convert kernels (fp32 -> fp16) ----------------------------
__global__ __launch_bounds__(256)
void split_x_kernel(const float* __restrict__ src)
{
    size_t i = ((size_t)blockIdx.x * 256 + threadIdx.x) * 4;
    if (i >= (size_t)N_TOKENS * D_IN) return;
    float4 v = *(const float4*)(src + i);
    *(__half2*)(g_x1 + i)     = __half2{__float2half_rn(v.x), __float2half_rn(v.y)};
    *(__half2*)(g_x1 + i + 2) = __half2{__float2half_rn(v.z), __float2half_rn(v.w)};
}

__global__ __launch_bounds__(256)
void split_w_kernel(const float* __restrict__ src)
{
    size_t i = ((size_t)blockIdx.x * 256 + threadIdx.x) * 4;
    if (i >= (size_t)D_HIDDEN * D_IN) return;
    float4 v = *(const float4*)(src + i);
    *(__half2*)(g_w1 + i)     = __half2{__float2half_rn(v.x), __float2half_rn(v.y)};
    *(__half2*)(g_w1 + i + 2) = __half2{__float2half_rn(v.z), __float2half_rn(v.w)};
}

// ---------------- encode: fp16 x*w GEMM on mma.sync (R7 config, verbatim) ---
// CTA tile 128(tok) x 128(hid), BK=64, 8 warps 2x4, warp tile 64x32.
// SMEM stage: X|W (2 x 16KB, XOR chunk swizzle), 3-stage cp.async pipeline,
// 96KB smem -> 2 CTAs/SM (launch_bounds caps regs at 128).
#define EBK 64
#define ARR_BYTES 16384
#define STAGE_BYTES (2 * ARR_BYTES)      // 32KB
#define ENC_SMEM (3 * STAGE_BYTES)       // 96KB
#define N_STAGES (D_IN / EBK)            // 64

__global__ __launch_bounds__(256, 2)
void encode_mma_kernel(const float* __restrict__ bias, float* __restrict__ feat)
{
    extern __shared__ __align__(128) char smem[];
    const int tid  = threadIdx.x;
    const int wid  = tid >> 5;
    const int lane = tid & 31;
    const int wm   = wid >> 2;       // 0..1
    const int wn   = wid & 3;        // 0..3
    const int bn   = blockIdx.x * 128;   // token tile (fastest -> B tile L2-hot)
    const int bh   = blockIdx.y * 128;   // hidden tile
    const uint32_t smem_base = smem_u32(smem);

    float acc[4][4][4];
#pragma unroll
    for (int mt = 0; mt < 4; ++mt)
#pragma unroll
        for (int nt = 0; nt < 4; ++nt)
#pragma unroll
            for (int q = 0; q < 4; ++q) acc[mt][nt][q] = 0.0f;

#define PREFETCH(s) do {                                                          \
    const int _k0 = (s) * EBK;                                                    \
    const uint32_t _st = smem_base + ((s) % 3) * STAGE_BYTES;                     \
    _Pragma("unroll")                                                             \
    for (int _l = 0; _l < 4; ++_l) {                                              \
        int _id = _l * 256 + tid;                                                 \
        int _r = _id >> 3, _c = _id & 7;                                          \
        uint32_t _sw = (uint32_t)(_r * 128 + ((_c ^ (_r & 7)) << 4));             \
        size_t _ga = (size_t)(bn + _r) * D_IN + _k0 + _c * 8;                     \
        size_t _gb = (size_t)(bh + _r) * D_IN + _k0 + _c * 8;                     \
        cp16(_st + 0 * ARR_BYTES + _sw, g_x1 + _ga);                              \
        cp16(_st + 1 * ARR_BYTES + _sw, g_w1 + _gb);                              \
    }                                                                             \
    CP_COMMIT();                                                                  \
} while (0)

    PREFETCH(0);
    PREFETCH(1);

    const int rA_base = wm * 64 + (lane & 15);
    const int rB_base = wn * 32 + (lane & 7);

    for (int s = 0; s < N_STAGES; ++s) {
        if (s + 2 < N_STAGES) {
            CP_WAIT1();
            __syncthreads();
            PREFETCH(s + 2);
        } else {
            CP_WAIT0();
            __syncthreads();
        }
        const uint32_t st = smem_base + (s % 3) * STAGE_BYTES;

#pragma unroll
        for (int ks = 0; ks < 4; ++ks) {
            uint32_t a[4][4], b[4][2];
            const int cA = 2 * ks + (lane >> 4);
#pragma unroll
            for (int mt = 0; mt < 4; ++mt) {
                int r = rA_base + mt * 16;
                uint32_t off = st + (uint32_t)(r * 128 + ((cA ^ (r & 7)) << 4));
                LDSM_X4(a[mt], off);
            }
            const int cB = 2 * ks + ((lane >> 3) & 1);
#pragma unroll
            for (int nt = 0; nt < 4; ++nt) {
                int r = rB_base + nt * 8;
                uint32_t off = st + ARR_BYTES + (uint32_t)(r * 128 + ((cB ^ (r & 7)) << 4));
                LDSM_X2(b[nt], off);
            }
#pragma unroll
            for (int mt = 0; mt < 4; ++mt)
#pragma unroll
                for (int nt = 0; nt < 4; ++nt)
                    mma16816(acc[mt][nt], a[mt], b[nt]);
        }
        __syncthreads();
    }
#undef PREFETCH

    // Epilogue: +bias, ReLU, store fp32
#pragma unroll
    for (int mt = 0; mt < 4; ++mt) {
        const int row0 = bn + wm * 64 + mt * 16 + (lane >> 2);
#pragma unroll
        for (int nt = 0; nt < 4; ++nt) {
            const int col0 = bh + wn * 32 + nt * 8 + (lane & 3) * 2;
            const float bb0 = bias[col0], bb1 = bias[col0 + 1];
            float2 v0, v1;
            v0.x = acc[mt][nt][0] + bb0; v0.x = v0.x > 0.0f ? v0.x : 0.0f;
            v0.y = acc[mt][nt][1] + bb1; v0.y = v0.y > 0.0f ? v0.y : 0.0f;
            v1.x = acc[mt][nt][2] + bb0; v1.x = v1.x > 0.0f ? v1.x : 0.0f;
            v1.y = acc[mt][nt][3] + bb1; v1.y = v1.y > 0.0f ? v1.y : 0.0f;
            *(float2*)&feat[(size_t)row0 * D_HIDDEN + col0]       = v0;
            *(float2*)&feat[(size_t)(row0 + 8) * D_HIDDEN + col0] = v1;
        }
    }
}

// ---------------- top-k: 1-pass linear histogram + margin classify ----------
__global__ __launch_bounds__(256)
void topk_kernel(float* __restrict__ feat)
{
    const int n   = blockIdx.x;
    const int tid = threadIdx.x;
    float* row = feat + (size_t)n * D_HIDDEN;

    __shared__ int hist[4096];
    __shared__ int s_part[256];
    __shared__ int s_bin;
    __shared__ int s_ndef, s_ncand;

    for (int i = tid; i < 4096; i += 256) hist[i] = 0;
    if (tid == 0) { s_bin = 0; s_ndef = 0; s_ncand = 0; }
    __syncthreads();

    for (int i = tid; i < D_HIDDEN; i += 256) {
        float v = row[i];
        if (v > 0.0f) {
            int b = (int)(v * 512.0f);
            if (b > 4095) b = 4095;
            atomicAdd(&hist[b], 1);
        }
    }
    __syncthreads();

    const int hi_b = 4095 - tid * 16;
    int part = 0;
#pragma unroll
    for (int j = 0; j < 16; ++j) part += hist[hi_b - j];
    s_part[tid] = part;
    __syncthreads();
    for (int off = 1; off < 256; off <<= 1) {
        int v2 = (tid >= off) ? s_part[tid - off] : 0;
        __syncthreads();
        s_part[tid] += v2;
        __syncthreads();
    }
    const int incl = s_part[tid];
    const int excl = incl - part;
    if (excl < TOPK && incl >= TOPK) {
        int cum = excl;
        for (int j = 0; j < 16; ++j) {
            cum += hist[hi_b - j];
            if (cum >= TOPK) { s_bin = hi_b - j; break; }
        }
    }
    __syncthreads();

    const float lo = (float)s_bin / 512.0f - MARGIN;
    const float hi = (float)(s_bin + 1) / 512.0f + MARGIN;

    for (int i = tid; i < D_HIDDEN; i += 256) {
        float v = row[i];
        if (v > hi) {
            int p = atomicAdd(&s_ndef, 1);
            g_topk_idx[n * TOPK + p] = i;
            g_topk_val[n * TOPK + p] = v;
        } else {
            if (v >= lo) {
                int q = atomicAdd(&s_ncand, 1);
                if (q < 64) { g_cand_idx[n * 64 + q] = i; g_cand_val[n * 64 + q] = v; }
            }
            row[i] = 0.0f;
        }
    }
    __syncthreads();
    if (tid == 0) {
        g_ndef[n]  = s_ndef;
        g_ncand[n] = s_ncand < 64 ? s_ncand : 64;
    }
}

// ---------------- rerank: exact fp64 scoring of boundary candidates ---------
__global__ __launch_bounds__(256)
void rerank_kernel(const float* __restrict__ x, const float* __restrict__ W_enc,
                   const float* __restrict__ b_enc, float* __restrict__ feat)
{
    __shared__ float  sx[D_IN];
    __shared__ double sred[256];
    __shared__ double s_exact[64];

    const int n   = blockIdx.x;
    const int tid = threadIdx.x;
    const int ndef  = g_ndef[n];
    const int ncand = g_ncand[n];
    const int need  = TOPK - ndef;
    float* row = feat + (size_t)n * D_HIDDEN;

    if (need <= 0) return;

    if (ncand <= need) {
        for (int c = tid; c < ncand; c += 256) {
            int idx = g_cand_idx[n * 64 + c];
            float v = g_cand_val[n * 64 + c];
            row[idx] = v;
            g_topk_idx[n * TOPK + ndef + c] = idx;
            g_topk_val[n * TOPK + ndef + c] = v;
        }
        return;
    }

    for (int i = tid * 4; i < D_IN; i += 1024)
        *(float4*)&sx[i] = *(const float4*)(x + (size_t)n * D_IN + i);
    __syncthreads();

    for (int c = 0; c < ncand; ++c) {
        const float* w = W_enc + (size_t)g_cand_idx[n * 64 + c] * D_IN;
        double acc = 0.0;
        for (int j = tid; j < D_IN; j += 256)
            acc += (double)sx[j] * (double)w[j];
        sred[tid] = acc;
        __syncthreads();
        for (int st = 128; st > 0; st >>= 1) {
            if (tid < st) sred[tid] += sred[tid + st];
            __syncthreads();
        }
        if (tid == 0) {
            double v = sred[0] + (double)b_enc[g_cand_idx[n * 64 + c]];
            s_exact[c] = v > 0.0 ? v : 0.0;
        }
        __syncthreads();
    }

    if (tid == 0) {
        bool used[64];
        for (int c = 0; c < ncand; ++c) used[c] = false;
        for (int r = 0; r < need; ++r) {
            int best = -1;
            for (int c = 0; c < ncand; ++c) {
                if (used[c]) continue;
                if (best < 0 || s_exact[c] > s_exact[best] ||
                    (s_exact[c] == s_exact[best] &&
                     g_cand_idx[n * 64 + c] < g_cand_idx[n * 64 + best]))
                    best = c;
            }
            used[best] = true;
            int idx = g_cand_idx[n * 64 + best];
            float v = g_cand_val[n * 64 + best];
            row[idx] = v;
            g_topk_idx[n * TOPK + ndef + r] = idx;
            g_topk_val[n * TOPK + ndef + r] = v;
        }
    }
}

// ---------------- transpose W_dec [d][h] -> g_wdecT fp16 [h][d] -------------
__global__ __launch_bounds__(256)
void transpose_kernel(const float* __restrict__ W)
{
    __shared__ float t[32][65];     // [h][d]
    const int h0 = blockIdx.x * 32;
    const int d0 = blockIdx.y * 64;
    const int tx = threadIdx.x;     // 0..31
    const int ty = threadIdx.y;     // 0..7

#pragma unroll
    for (int i = 0; i < 64; i += 8)
        t[tx][i + ty] = W[(size_t)(d0 + i + ty) * D_HIDDEN + h0 + tx];
    __syncthreads();
#pragma unroll
    for (int i = 0; i < 32; i += 8) {
        const int h = i + ty;
        __half2 hv = __half2{__float2half_rn(t[h][2 * tx]),
                             __float2half_rn(t[h][2 * tx + 1])};
        *(__half2*)(g_wdecT + (size_t)(h0 + h) * D_IN + d0 + 2 * tx) = hv;
    }
}

// ---------------- sparse decode (fp16 weights, fp32 accum) ------------------
__global__ __launch_bounds__(256)
void decode_kernel(float* __restrict__ recon, const float* __restrict__ b_dec)
{
    const int n   = blockIdx.x;
    const int tid = threadIdx.x;

    __shared__ int   s_idx[TOPK];
    __shared__ float s_val[TOPK];
    if (tid < TOPK) {
        s_idx[tid] = g_topk_idx[n * TOPK + tid];
        s_val[tid] = g_topk_val[n * TOPK + tid];
    }
    __syncthreads();

    float acc[16];
#pragma unroll
    for (int r = 0; r < 8; ++r) {
        float2 b = *(const float2*)(b_dec + 2 * (tid + r * 256));
        acc[2 * r] = b.x; acc[2 * r + 1] = b.y;
    }

    for (int j = 0; j < TOPK; ++j) {
        const __half2* wr = (const __half2*)(g_wdecT + (size_t)s_idx[j] * D_IN);
        const float v = s_val[j];
#pragma unroll
        for (int r = 0; r < 8; ++r) {
            float2 w = __half22float2(wr[tid + r * 256]);
            acc[2 * r]     += v * w.x;
            acc[2 * r + 1] += v * w.y;
        }
    }

    float* out = recon + (size_t)n * D_IN;
#pragma unroll
    for (int r = 0; r < 8; ++r) {
        float2 o; o.x = acc[2 * r]; o.y = acc[2 * r + 1];
        *(float2*)(out + 2 * (tid + r * 256)) = o;
    }
}

// ---------------- launch -----------------------------------------------------
extern "C" void kernel_launch(void* const* d_in, const int* in_sizes, int n_in,
                              void* d_out, int out_size)
{
    const float* x     = (const float*)d_in[0];
    const float* W_enc = (const float*)d_in[1];
    const float* b_enc = (const float*)d_in[2];
    const float* W_dec = (const float*)d_in[3];
    const float* b_dec = (const float*)d_in[4];

    float* recon = (float*)d_out;
    float* feat  = (float*)d_out + (size_t)N_TOKENS * D_IN;

    cudaFuncSetAttribute(encode_mma_kernel,
                         cudaFuncAttributeMaxDynamicSharedMemorySize, ENC_SMEM);

    split_x_kernel<<<(N_TOKENS * D_IN) / 1024, 256>>>(x);
    split_w_kernel<<<((size_t)D_HIDDEN * D_IN) / 1024, 256>>>(W_enc);
    transpose_kernel<<<dim3(D_HIDDEN / 32, D_IN / 64), dim3(32, 8)>>>(W_dec);

    encode_mma_kernel<<<dim3(N_TOKENS / 128, D_HIDDEN / 128), 256, ENC_SMEM>>>(b_enc, feat);

    topk_kernel<<<N_TOKENS, 256>>>(feat);
    rerank_kernel<<<N_TOKENS, 256>>>(x, W_enc, b_enc, feat);
    decode_kernel<<<N_TOKENS, 256>>>(recon, b_dec);
}